// round 13
// baseline (speedup 1.0000x reference)
#include <cuda_runtime.h>
#include <cuda_fp16.h>
#include <cstdint>
#include <math.h>

#define E    1024
#define Dh   64
#define H    16
#define Ff   4096
#define Bb   2
#define Ss   2048
#define NT   (Bb*Ss)     // 4096 tokens
#define EPS  1e-5f

// ---------------- scratch (static device memory; no allocation) ----------------
__device__ __half g_h   [NT * E];        // LN1 output (fp16)
__device__ float  g_qkv [NT * 3 * E];    // fused q|k|v, row stride 3072 (fp32)
__device__ __half g_Wqkv[3 * E * E];     // packed W_qkv^T : [3072, 1024] (N,K) fp16
__device__ float  g_bqkv[3 * E];
__device__ __half g_WoT [E * E];         // Wo^T  fp16
__device__ __half g_W1T [Ff * E];        // W1^T  fp16
__device__ __half g_W2T [E * Ff];        // W2^T  fp16
__device__ __half g_o   [NT * E];        // attention out (fp16)
__device__ float  g_x1  [NT * E];        // after first residual (fp32)
__device__ __half g_h2  [NT * E];        // LN2 output (fp16)
__device__ __half g_m1  [NT * Ff];       // relu(h2 @ W1 + b1) (fp16)

// ======================= helpers =======================
__device__ __forceinline__ uint32_t smem_u32(const void* p) {
    uint32_t a;
    asm("{ .reg .u64 t; cvta.to.shared.u64 t, %1; cvt.u32.u64 %0, t; }" : "=r"(a) : "l"(p));
    return a;
}
__device__ __forceinline__ uint32_t f22h2(float a, float b) {
    __half2 h = __floats2half2_rn(a, b);
    return *(uint32_t*)&h;
}
#define CP_ASYNC16(dst, src) \
    asm volatile("cp.async.cg.shared.global [%0], [%1], 16;" :: "r"((uint32_t)(dst)), "l"(src))
#define CP_COMMIT() asm volatile("cp.async.commit_group;" ::: "memory")
#define CP_WAIT0()  asm volatile("cp.async.wait_group 0;" ::: "memory")
#define CP_WAIT1()  asm volatile("cp.async.wait_group 1;" ::: "memory")

#define LDMX4(r0, r1, r2, r3, addr) \
    asm volatile("ldmatrix.sync.aligned.m8n8.x4.shared.b16 {%0,%1,%2,%3}, [%4];" \
        : "=r"(r0), "=r"(r1), "=r"(r2), "=r"(r3) : "r"(addr))

// m16n8k16 fp16 mma: D(f32) += A(f16) * B(f16)
__device__ __forceinline__ void mma_f16(float* c, const uint32_t* a, uint32_t b0, uint32_t b1) {
    asm volatile(
        "mma.sync.aligned.m16n8k16.row.col.f32.f16.f16.f32 "
        "{%0,%1,%2,%3}, {%4,%5,%6,%7}, {%8,%9}, {%0,%1,%2,%3};"
        : "+f"(c[0]), "+f"(c[1]), "+f"(c[2]), "+f"(c[3])
        : "r"(a[0]), "r"(a[1]), "r"(a[2]), "r"(a[3]), "r"(b0), "r"(b1));
}

// ---------------- weight packing (fp16) ----------------
__global__ void pack_qkv_kernel(const float* __restrict__ Wq, const float* __restrict__ Wk,
                                const float* __restrict__ Wv, const float* __restrict__ bq,
                                const float* __restrict__ bk, const float* __restrict__ bv) {
    int i = blockIdx.x * blockDim.x + threadIdx.x;
    if (i < 3 * E * E) {
        int n = i >> 10;            // 0..3071
        int e = i & 1023;
        int wh = n >> 10;           // 0=q 1=k 2=v
        int hd = n & 1023;
        int h = hd >> 6, d = hd & 63;
        const float* W = (wh == 0) ? Wq : (wh == 1) ? Wk : Wv;
        g_Wqkv[i] = __float2half_rn(W[(h * E + e) * Dh + d]);
    }
    if (i < 3 * E) {
        const float* bs = (i < E) ? bq : (i < 2 * E) ? bk : bv;
        g_bqkv[i] = bs[i % E];
    }
}

// out[n*K + k] = fp16(in[k*N + n])
__global__ void transpose_kernel(const float* __restrict__ in, __half* __restrict__ out,
                                 int K, int N) {
    __shared__ float t[32][33];
    int k0 = blockIdx.x * 32, n0 = blockIdx.y * 32;
    int x = threadIdx.x, y = threadIdx.y;     // 32 x 8
    #pragma unroll
    for (int i = 0; i < 32; i += 8)
        t[y + i][x] = in[(size_t)(k0 + y + i) * N + n0 + x];
    __syncthreads();
    #pragma unroll
    for (int i = 0; i < 32; i += 8)
        out[(size_t)(n0 + y + i) * K + k0 + x] = __float2half_rn(t[x][y + i]);
}

// ---------------- layernorm (fp16 output) ----------------
__global__ void ln_kernel(const float* __restrict__ x, const float* __restrict__ g,
                          const float* __restrict__ b, __half* __restrict__ out) {
    int row = blockIdx.x;
    int tid = threadIdx.x;
    const float4 v = ((const float4*)(x + (size_t)row * E))[tid];
    float s  = v.x + v.y + v.z + v.w;
    float ss = v.x * v.x + v.y * v.y + v.z * v.z + v.w * v.w;
    #pragma unroll
    for (int o = 16; o; o >>= 1) {
        s  += __shfl_xor_sync(0xffffffffu, s,  o);
        ss += __shfl_xor_sync(0xffffffffu, ss, o);
    }
    __shared__ float sm[8], sm2[8];
    if ((tid & 31) == 0) { sm[tid >> 5] = s; sm2[tid >> 5] = ss; }
    __syncthreads();
    float tot = 0.f, tot2 = 0.f;
    #pragma unroll
    for (int i = 0; i < 8; i++) { tot += sm[i]; tot2 += sm2[i]; }
    float mean = tot * (1.0f / E);
    float var  = tot2 * (1.0f / E) - mean * mean;
    float inv  = rsqrtf(var + EPS);
    const float4 gg = ((const float4*)g)[tid];
    const float4 bb = ((const float4*)b)[tid];
    __half2* orow = (__half2*)(out + (size_t)row * E);
    orow[2 * tid]     = __floats2half2_rn((v.x - mean) * inv * gg.x + bb.x,
                                          (v.y - mean) * inv * gg.y + bb.y);
    orow[2 * tid + 1] = __floats2half2_rn((v.z - mean) * inv * gg.z + bb.z,
                                          (v.w - mean) * inv * gg.w + bb.w);
}

// ---------------- fp16 warp-MMA GEMM: C = A[M,K] @ Bt[N,K]^T (+bias)(+relu)(+res)
// CTA tile 128x128, 8 warps (32x64 each), K-chunk 64 halves, 3-stage cp.async.
// ldmatrix.x4 fragment loads; B loaded just-in-time to cap register liveness.
#define LDH 72
#define TILE_H (128 * LDH * 2)          // 18432 bytes per tile
#define STAGE_H (2 * TILE_H)            // 36864
#define GEMMH_SMEM (3 * STAGE_H)        // 110592 -> 2 CTAs/SM

template<bool RELU, bool OUT_HALF>
__global__ __launch_bounds__(256, 2)
void gemm_h(const __half* __restrict__ A, const __half* __restrict__ Bt,
            const float* __restrict__ bias, const float* __restrict__ res,
            void* __restrict__ Cv, int M, int N, int K) {
    extern __shared__ char smem[];
    uint32_t sb = smem_u32(smem);
    int tid = threadIdx.x;
    int lane = tid & 31, wid = tid >> 5;
    int warp_m = wid & 3, warp_n = wid >> 2;        // 4 x 2 warp grid, warp 32x64
    int n0 = blockIdx.x * 128, m0 = blockIdx.y * 128;

    const __half* Abase = A  + (size_t)m0 * K;
    const __half* Bbase = Bt + (size_t)n0 * K;

    int NC = K >> 6;   // chunks of 64 halves

    // ldmatrix per-thread byte offsets (within a stage)
    int lt = lane >> 3, lr = lane & 7;
    uint32_t aoff[2], boff[4];
    #pragma unroll
    for (int mt = 0; mt < 2; mt++)
        aoff[mt] = ((warp_m * 32 + mt * 16 + (lt & 1) * 8 + lr) * 36 + (lt >> 1) * 4) * 4;
    #pragma unroll
    for (int nt2 = 0; nt2 < 4; nt2++)
        boff[nt2] = TILE_H + ((warp_n * 64 + nt2 * 16 + (lt & 1) * 8 + lr) * 36 + (lt >> 1) * 4) * 4;

    // prologue: chunks 0,1 -> stages 0,1
    #pragma unroll
    for (int st = 0; st < 2; st++) {
        uint32_t bufo = st * STAGE_H;
        int koff = st * 64;
        #pragma unroll
        for (int i = 0; i < 4; i++) {
            int idx = tid + i * 256;               // 1024 A slots
            int row = idx >> 3, seg = idx & 7;
            CP_ASYNC16(sb + bufo + row * 144 + seg * 16,
                       Abase + (size_t)row * K + koff + seg * 8);
        }
        #pragma unroll
        for (int i = 0; i < 4; i++) {
            int idx = tid + i * 256;               // 1024 B slots
            int row = idx >> 3, seg = idx & 7;
            CP_ASYNC16(sb + bufo + TILE_H + row * 144 + seg * 16,
                       Bbase + (size_t)row * K + koff + seg * 8);
        }
        CP_COMMIT();
    }
    CP_WAIT1();
    __syncthreads();

    float acc[2][8][4] = {};
    int cb = 0, pb = 2;

    int r = lane >> 2, cc = lane & 3;

    for (int c = 0; c < NC; c++) {
        if (c + 2 < NC) {
            uint32_t bufo = pb * STAGE_H;
            const __half* as = Abase + (c + 2) * 64;
            const __half* bs = Bbase + (c + 2) * 64;
            #pragma unroll
            for (int i = 0; i < 4; i++) {
                int idx = tid + i * 256;
                int row = idx >> 3, seg = idx & 7;
                CP_ASYNC16(sb + bufo + row * 144 + seg * 16,
                           as + (size_t)row * K + seg * 8);
            }
            #pragma unroll
            for (int i = 0; i < 4; i++) {
                int idx = tid + i * 256;
                int row = idx >> 3, seg = idx & 7;
                CP_ASYNC16(sb + bufo + TILE_H + row * 144 + seg * 16,
                           bs + (size_t)row * K + seg * 8);
            }
        }
        CP_COMMIT();

        uint32_t stage = sb + cb * STAGE_H;

        #pragma unroll
        for (int kk = 0; kk < 4; kk++) {           // 4 k16-steps
            uint32_t koff = kk * 32;               // 8 uint32 = 32 bytes
            uint32_t afr[2][4];
            LDMX4(afr[0][0], afr[0][1], afr[0][2], afr[0][3], stage + aoff[0] + koff);
            LDMX4(afr[1][0], afr[1][1], afr[1][2], afr[1][3], stage + aoff[1] + koff);
            #pragma unroll
            for (int nt2 = 0; nt2 < 4; nt2++) {
                uint32_t bfr[4];                   // just-in-time B frags (4 live regs)
                LDMX4(bfr[0], bfr[1], bfr[2], bfr[3], stage + boff[nt2] + koff);
                mma_f16(acc[0][2 * nt2    ], afr[0], bfr[0], bfr[2]);
                mma_f16(acc[1][2 * nt2    ], afr[1], bfr[0], bfr[2]);
                mma_f16(acc[0][2 * nt2 + 1], afr[0], bfr[1], bfr[3]);
                mma_f16(acc[1][2 * nt2 + 1], afr[1], bfr[1], bfr[3]);
            }
        }
        CP_WAIT1();
        __syncthreads();
        cb = (cb + 1 == 3) ? 0 : cb + 1;
        pb = (pb + 1 == 3) ? 0 : pb + 1;
    }

    // epilogue
    #pragma unroll
    for (int mt = 0; mt < 2; mt++) {
        #pragma unroll
        for (int nt = 0; nt < 8; nt++) {
            int col = n0 + warp_n * 64 + nt * 8 + cc * 2;
            float2 bv = *(const float2*)&bias[col];
            #pragma unroll
            for (int rr = 0; rr < 2; rr++) {
                int row = m0 + warp_m * 32 + mt * 16 + r + rr * 8;
                float vx = acc[mt][nt][rr * 2 + 0] + bv.x;
                float vy = acc[mt][nt][rr * 2 + 1] + bv.y;
                if (RELU) { vx = fmaxf(vx, 0.f); vy = fmaxf(vy, 0.f); }
                if (res) {
                    float2 rv = *(const float2*)&res[(size_t)row * N + col];
                    vx += rv.x; vy += rv.y;
                }
                if (OUT_HALF) {
                    *(uint32_t*)&((__half*)Cv)[(size_t)row * N + col] = f22h2(vx, vy);
                } else {
                    float2 v = { vx, vy };
                    *(float2*)&((float*)Cv)[(size_t)row * N + col] = v;
                }
            }
        }
    }
}

// ---------------- fp16 MMA flash attention (rows = keys, softmax over queries) --
// R12 structure; S/PV fragment loads converted to ldmatrix.x4 (mapping verified
// bit-exact in R11). P stays in smem; __syncwarp kept.
#define QRAW_F 0
#define VRAW_F (64 * 68)
#define KF_F   (VRAW_F + 64 * 72)
#define PU_OFF (KF_F)                    // uint index == float index
#define VHU_OFF (KF_F + 128 * 36)
#define QHI_OFF (KF_F + 128 * 68)
#define QLO_OFF (QHI_OFF + 64 * 36)
#define ATT_SMEM ((QLO_OFF + 64 * 36) * 4)   // 89088 bytes

__global__ __launch_bounds__(256)
void attn_mma_kernel(const float* __restrict__ qkv, __half* __restrict__ o_out) {
    extern __shared__ float smf[];
    uint32_t sb = smem_u32(smf);
    uint32_t* smu = (uint32_t*)smf;

    int hb = blockIdx.y;
    int hh = hb >> 1, b = hb & 1;
    int s0 = blockIdx.x * 128;
    int tid = threadIdx.x, lane = tid & 31, wid = tid >> 5;
    int r = lane >> 2, cc = lane & 3;
    int rb = wid * 16 + r;

    // ldmatrix per-thread byte offsets
    int lt = lane >> 3, lr = lane & 7;
    uint32_t qhio[4], qloo[4], voff[4], poff;
    {
        uint32_t rowsel = (lt & 1) * 8 + lr;
        uint32_t wordsel = (lt >> 1) * 4;
        #pragma unroll
        for (int nt2 = 0; nt2 < 4; nt2++) {
            uint32_t ro = ((nt2 * 16 + rowsel) * 36 + wordsel) * 4;
            qhio[nt2] = QHI_OFF * 4 + ro;
            qloo[nt2] = QLO_OFF * 4 + ro;
            voff[nt2] = VHU_OFF * 4 + ro;
        }
        poff = PU_OFF * 4 + ((wid * 16 + rowsel) * 36 + wordsel) * 4;
    }

    const float* base = qkv + (size_t)(b * Ss) * 3072 + hh * 64;

    // K tile [128 x 64] fp32 (group 0)
    #pragma unroll
    for (int i = 0; i < 8; i++) {
        int idx = tid + i * 256;               // 0..2047
        int row = idx >> 4, seg = idx & 15;
        CP_ASYNC16(sb + (KF_F + row * 68) * 4 + seg * 16,
                   base + 1024 + (size_t)(s0 + row) * 3072 + seg * 4);
    }
    CP_COMMIT();
    // Q(0), V(0) (group 1)
    #pragma unroll
    for (int i = 0; i < 4; i++) {
        int idx = tid + i * 256;               // 0..1023
        int row = idx >> 4, seg = idx & 15;
        CP_ASYNC16(sb + (QRAW_F + row * 68) * 4 + seg * 16,
                   base + (size_t)row * 3072 + seg * 4);
        CP_ASYNC16(sb + (VRAW_F + row * 72) * 4 + seg * 16,
                   base + 2048 + (size_t)row * 3072 + seg * 4);
    }
    CP_COMMIT();
    CP_WAIT1();              // K resident
    __syncthreads();

    // K fragments hi/lo fp16 in registers: m16 x k64 (4 k16-steps)
    uint32_t kfh[4][4], kfl[4][4];
    #pragma unroll
    for (int kk = 0; kk < 4; kk++) {
        float2 kv[4];
        kv[0] = *(float2*)&smf[KF_F + (rb    ) * 68 + kk * 16 + 2 * cc];
        kv[1] = *(float2*)&smf[KF_F + (rb + 8) * 68 + kk * 16 + 2 * cc];
        kv[2] = *(float2*)&smf[KF_F + (rb    ) * 68 + kk * 16 + 2 * cc + 8];
        kv[3] = *(float2*)&smf[KF_F + (rb + 8) * 68 + kk * 16 + 2 * cc + 8];
        #pragma unroll
        for (int j = 0; j < 4; j++) {
            float hx = __half2float(__float2half_rn(kv[j].x));
            float hy = __half2float(__float2half_rn(kv[j].y));
            kfh[kk][j] = f22h2(hx, hy);
            kfl[kk][j] = f22h2(kv[j].x - hx, kv[j].y - hy);
        }
    }

    float mrow0 = -1e30f, mrow1 = -1e30f, lrow0 = 0.f, lrow1 = 0.f;
    float o[8][4] = {};

    int vd = (lane & 31) + 32 * (wid & 1);     // V-convert: this thread's d
    int vq = (vd >> 3) & 3;
    int vcb = (wid >> 1) * 8;

    for (int t0 = 0; t0 < Ss; t0 += 64) {
        CP_WAIT0();
        __syncthreads();       // Q(t)/V(t) resident; prior tile smem reads done

        // convert Q -> Qhi/Qlo (half2)
        #pragma unroll
        for (int i = 0; i < 8; i++) {
            int slot = tid + i * 256;          // 0..2047
            int t = slot >> 5, dp = slot & 31;
            float2 q = *(float2*)&smf[QRAW_F + t * 68 + 2 * dp];
            float hx = __half2float(__float2half_rn(q.x));
            float hy = __half2float(__float2half_rn(q.y));
            smu[QHI_OFF + t * 36 + dp] = f22h2(hx, hy);
            smu[QLO_OFF + t * 36 + dp] = f22h2(q.x - hx, q.y - hy);
        }
        // convert V -> Vh[d][t] (half2, transposed, xor-permuted write order)
        #pragma unroll
        for (int i = 0; i < 8; i++) {
            int tp = (vcb + i) ^ vq;
            float va = smf[VRAW_F + (2 * tp    ) * 72 + vd];
            float vb = smf[VRAW_F + (2 * tp + 1) * 72 + vd];
            smu[VHU_OFF + vd * 36 + tp] = f22h2(va, vb);
        }
        __syncthreads();

        if (t0 + 64 < Ss) {
            const float* src = base + (size_t)(t0 + 64) * 3072;
            #pragma unroll
            for (int i = 0; i < 4; i++) {
                int idx = tid + i * 256;
                int row = idx >> 4, seg = idx & 15;
                CP_ASYNC16(sb + (QRAW_F + row * 68) * 4 + seg * 16,
                           src + (size_t)row * 3072 + seg * 4);
                CP_ASYNC16(sb + (VRAW_F + row * 72) * 4 + seg * 16,
                           src + 2048 + (size_t)row * 3072 + seg * 4);
            }
            CP_COMMIT();
        }

        // S = K x Q^T : split-fp16 (3 MMAs per k16-step), Q frags via ldmatrix
        float s[8][4] = {};
        #pragma unroll
        for (int kk = 0; kk < 4; kk++) {
            uint32_t koff = kk * 32;
            #pragma unroll
            for (int nt2 = 0; nt2 < 4; nt2++) {
                uint32_t qh[4], ql[4];
                LDMX4(qh[0], qh[1], qh[2], qh[3], sb + qhio[nt2] + koff);
                LDMX4(ql[0], ql[1], ql[2], ql[3], sb + qloo[nt2] + koff);
                mma_f16(s[2 * nt2    ], kfh[kk], qh[0], qh[2]);
                mma_f16(s[2 * nt2    ], kfh[kk], ql[0], ql[2]);
                mma_f16(s[2 * nt2    ], kfl[kk], qh[0], qh[2]);
                mma_f16(s[2 * nt2 + 1], kfh[kk], qh[1], qh[3]);
                mma_f16(s[2 * nt2 + 1], kfh[kk], ql[1], ql[3]);
                mma_f16(s[2 * nt2 + 1], kfl[kk], qh[1], qh[3]);
            }
        }

        // online softmax over t (rows in-warp: quad shfl reduce)
        float mx0 = -1e30f, mx1 = -1e30f;
        #pragma unroll
        for (int nt = 0; nt < 8; nt++) {
            mx0 = fmaxf(mx0, fmaxf(s[nt][0], s[nt][1]));
            mx1 = fmaxf(mx1, fmaxf(s[nt][2], s[nt][3]));
        }
        mx0 = fmaxf(mx0, __shfl_xor_sync(0xffffffffu, mx0, 1));
        mx0 = fmaxf(mx0, __shfl_xor_sync(0xffffffffu, mx0, 2));
        mx1 = fmaxf(mx1, __shfl_xor_sync(0xffffffffu, mx1, 1));
        mx1 = fmaxf(mx1, __shfl_xor_sync(0xffffffffu, mx1, 2));
        float mn0 = fmaxf(mrow0, mx0), mn1 = fmaxf(mrow1, mx1);
        float a0 = __expf(mrow0 - mn0), a1 = __expf(mrow1 - mn1);
        mrow0 = mn0; mrow1 = mn1;

        float ps0 = 0.f, ps1 = 0.f;
        #pragma unroll
        for (int nt = 0; nt < 8; nt++) {
            float p0 = __expf(s[nt][0] - mn0);
            float p1 = __expf(s[nt][1] - mn0);
            float p2 = __expf(s[nt][2] - mn1);
            float p3 = __expf(s[nt][3] - mn1);
            ps0 += p0 + p1;
            ps1 += p2 + p3;
            smu[PU_OFF + (rb    ) * 36 + nt * 4 + cc] = f22h2(p0, p1);
            smu[PU_OFF + (rb + 8) * 36 + nt * 4 + cc] = f22h2(p2, p3);
        }
        ps0 += __shfl_xor_sync(0xffffffffu, ps0, 1);
        ps0 += __shfl_xor_sync(0xffffffffu, ps0, 2);
        ps1 += __shfl_xor_sync(0xffffffffu, ps1, 1);
        ps1 += __shfl_xor_sync(0xffffffffu, ps1, 2);
        lrow0 = lrow0 * a0 + ps0;
        lrow1 = lrow1 * a1 + ps1;
        #pragma unroll
        for (int nt = 0; nt < 8; nt++) {
            o[nt][0] *= a0; o[nt][1] *= a0;
            o[nt][2] *= a1; o[nt][3] *= a1;
        }
        __syncwarp();   // this warp's P rows visible (warp-private rows)

        // O += P x V (P A-frags + V B-frags via ldmatrix)
        #pragma unroll
        for (int kk = 0; kk < 4; kk++) {
            uint32_t koff = kk * 32;
            uint32_t pa[4];
            LDMX4(pa[0], pa[1], pa[2], pa[3], sb + poff + koff);
            #pragma unroll
            for (int nt2 = 0; nt2 < 4; nt2++) {
                uint32_t vf[4];
                LDMX4(vf[0], vf[1], vf[2], vf[3], sb + voff[nt2] + koff);
                mma_f16(o[2 * nt2    ], pa, vf[0], vf[2]);
                mma_f16(o[2 * nt2 + 1], pa, vf[1], vf[3]);
            }
        }
    }

    float i0 = 1.f / lrow0, i1 = 1.f / lrow1;
    uint32_t* orow0 = (uint32_t*)(o_out + (size_t)(b * Ss + s0 + rb) * E + hh * 64);
    uint32_t* orow1 = (uint32_t*)(o_out + (size_t)(b * Ss + s0 + rb + 8) * E + hh * 64);
    #pragma unroll
    for (int nt = 0; nt < 8; nt++) {
        orow0[nt * 4 + cc] = f22h2(o[nt][0] * i0, o[nt][1] * i0);
        orow1[nt * 4 + cc] = f22h2(o[nt][2] * i1, o[nt][3] * i1);
    }
}

// ---------------- host launch ----------------
extern "C" void kernel_launch(void* const* d_in, const int* in_sizes, int n_in,
                              void* d_out, int out_size) {
    const float* x     = (const float*)d_in[0];
    const float* Wq    = (const float*)d_in[1];
    const float* bq    = (const float*)d_in[2];
    const float* Wk    = (const float*)d_in[3];
    const float* bk    = (const float*)d_in[4];
    const float* Wv    = (const float*)d_in[5];
    const float* bv    = (const float*)d_in[6];
    const float* Wo    = (const float*)d_in[7];
    const float* bo    = (const float*)d_in[8];
    const float* ln1_g = (const float*)d_in[9];
    const float* ln1_b = (const float*)d_in[10];
    const float* ln2_g = (const float*)d_in[11];
    const float* ln2_b = (const float*)d_in[12];
    const float* W1    = (const float*)d_in[13];
    const float* b1    = (const float*)d_in[14];
    const float* W2    = (const float*)d_in[15];
    const float* b2    = (const float*)d_in[16];
    float* out = (float*)d_out;

    __half *p_h, *p_Wqkv, *p_WoT, *p_W1T, *p_W2T, *p_o, *p_h2, *p_m1;
    float *p_qkv, *p_bqkv, *p_x1;
    cudaGetSymbolAddress((void**)&p_h,    g_h);
    cudaGetSymbolAddress((void**)&p_qkv,  g_qkv);
    cudaGetSymbolAddress((void**)&p_Wqkv, g_Wqkv);
    cudaGetSymbolAddress((void**)&p_bqkv, g_bqkv);
    cudaGetSymbolAddress((void**)&p_WoT,  g_WoT);
    cudaGetSymbolAddress((void**)&p_W1T,  g_W1T);
    cudaGetSymbolAddress((void**)&p_W2T,  g_W2T);
    cudaGetSymbolAddress((void**)&p_o,    g_o);
    cudaGetSymbolAddress((void**)&p_x1,   g_x1);
    cudaGetSymbolAddress((void**)&p_h2,   g_h2);
    cudaGetSymbolAddress((void**)&p_m1,   g_m1);

    cudaFuncSetAttribute(gemm_h<false, false>, cudaFuncAttributeMaxDynamicSharedMemorySize, GEMMH_SMEM);
    cudaFuncSetAttribute(gemm_h<true,  true>,  cudaFuncAttributeMaxDynamicSharedMemorySize, GEMMH_SMEM);
    cudaFuncSetAttribute(attn_mma_kernel,      cudaFuncAttributeMaxDynamicSharedMemorySize, ATT_SMEM);

    // 1. pack fused QKV weight (transposed, fp16) + bias; transpose Wo, W1, W2 (fp16)
    pack_qkv_kernel<<<(3 * E * E + 255) / 256, 256>>>(Wq, Wk, Wv, bq, bk, bv);
    transpose_kernel<<<dim3(E / 32, E / 32),  dim3(32, 8)>>>(Wo, p_WoT, E, E);
    transpose_kernel<<<dim3(E / 32, Ff / 32), dim3(32, 8)>>>(W1, p_W1T, E, Ff);
    transpose_kernel<<<dim3(Ff / 32, E / 32), dim3(32, 8)>>>(W2, p_W2T, Ff, E);

    // 2. LN1 (fp16 out)
    ln_kernel<<<NT, 256>>>(x, ln1_g, ln1_b, p_h);

    // 3. fused QKV projection: [4096,1024] @ [1024,3072]  (fp32 out -> split-fp16 attn)
    gemm_h<false, false><<<dim3(3 * E / 128, NT / 128), 256, GEMMH_SMEM>>>(p_h, p_Wqkv, p_bqkv, nullptr, p_qkv, NT, 3 * E, E);

    // 4. attention (split-fp16 S, fp16 PV) -> fp16 o
    attn_mma_kernel<<<dim3(Ss / 128, H * Bb), 256, ATT_SMEM>>>(p_qkv, p_o);

    // 5. output projection + residual (fp32 out)
    gemm_h<false, false><<<dim3(E / 128, NT / 128), 256, GEMMH_SMEM>>>(p_o, p_WoT, bo, x, p_x1, NT, E, E);

    // 6. LN2 (fp16 out)
    ln_kernel<<<NT, 256>>>(p_x1, ln2_g, ln2_b, p_h2);

    // 7. MLP up + ReLU (fp16 out -> feeds MLP down as A)
    gemm_h<true, true><<<dim3(Ff / 128, NT / 128), 256, GEMMH_SMEM>>>(p_h2, p_W1T, b1, nullptr, p_m1, NT, Ff, E);

    // 8. MLP down + residual -> fp32 output
    gemm_h<false, false><<<dim3(E / 128, NT / 128), 256, GEMMH_SMEM>>>(p_m1, p_W2T, b2, p_x1, out, NT, E, Ff);
}

// round 14
// speedup vs baseline: 1.0780x; 1.0780x over previous
#include <cuda_runtime.h>
#include <cuda_fp16.h>
#include <cstdint>
#include <math.h>

#define E    1024
#define Dh   64
#define H    16
#define Ff   4096
#define Bb   2
#define Ss   2048
#define NT   (Bb*Ss)     // 4096 tokens
#define EPS  1e-5f

// ---------------- scratch (static device memory; no allocation) ----------------
__device__ __half g_h   [NT * E];        // LN1 output (fp16)
__device__ __half g_qhi [NT * E];        // Q hi fp16
__device__ __half g_qlo [NT * E];        // Q lo fp16 (residual)
__device__ float  g_k   [NT * E];        // K fp32
__device__ __half g_v   [NT * E];        // V fp16
__device__ __half g_Wqkv[3 * E * E];     // packed W_qkv^T : [3072, 1024] (N,K) fp16
__device__ float  g_bqkv[3 * E];
__device__ __half g_WoT [E * E];         // Wo^T  fp16
__device__ __half g_W1T [Ff * E];        // W1^T  fp16
__device__ __half g_W2T [E * Ff];        // W2^T  fp16
__device__ __half g_o   [NT * E];        // attention out (fp16)
__device__ float  g_x1  [NT * E];        // after first residual (fp32)
__device__ __half g_h2  [NT * E];        // LN2 output (fp16)
__device__ __half g_m1  [NT * Ff];       // relu(h2 @ W1 + b1) (fp16)

// ======================= helpers =======================
__device__ __forceinline__ uint32_t smem_u32(const void* p) {
    uint32_t a;
    asm("{ .reg .u64 t; cvta.to.shared.u64 t, %1; cvt.u32.u64 %0, t; }" : "=r"(a) : "l"(p));
    return a;
}
__device__ __forceinline__ uint32_t f22h2(float a, float b) {
    __half2 h = __floats2half2_rn(a, b);
    return *(uint32_t*)&h;
}
#define CP_ASYNC16(dst, src) \
    asm volatile("cp.async.cg.shared.global [%0], [%1], 16;" :: "r"((uint32_t)(dst)), "l"(src))
#define CP_COMMIT() asm volatile("cp.async.commit_group;" ::: "memory")
#define CP_WAIT0()  asm volatile("cp.async.wait_group 0;" ::: "memory")
#define CP_WAIT1()  asm volatile("cp.async.wait_group 1;" ::: "memory")

#define LDMX4(r0, r1, r2, r3, addr) \
    asm volatile("ldmatrix.sync.aligned.m8n8.x4.shared.b16 {%0,%1,%2,%3}, [%4];" \
        : "=r"(r0), "=r"(r1), "=r"(r2), "=r"(r3) : "r"(addr))
#define LDMX4T(r0, r1, r2, r3, addr) \
    asm volatile("ldmatrix.sync.aligned.m8n8.x4.trans.shared.b16 {%0,%1,%2,%3}, [%4];" \
        : "=r"(r0), "=r"(r1), "=r"(r2), "=r"(r3) : "r"(addr))

// m16n8k16 fp16 mma: D(f32) += A(f16) * B(f16)
__device__ __forceinline__ void mma_f16(float* c, const uint32_t* a, uint32_t b0, uint32_t b1) {
    asm volatile(
        "mma.sync.aligned.m16n8k16.row.col.f32.f16.f16.f32 "
        "{%0,%1,%2,%3}, {%4,%5,%6,%7}, {%8,%9}, {%0,%1,%2,%3};"
        : "+f"(c[0]), "+f"(c[1]), "+f"(c[2]), "+f"(c[3])
        : "r"(a[0]), "r"(a[1]), "r"(a[2]), "r"(a[3]), "r"(b0), "r"(b1));
}

// ---------------- weight packing (fp16) ----------------
__global__ void pack_qkv_kernel(const float* __restrict__ Wq, const float* __restrict__ Wk,
                                const float* __restrict__ Wv, const float* __restrict__ bq,
                                const float* __restrict__ bk, const float* __restrict__ bv) {
    int i = blockIdx.x * blockDim.x + threadIdx.x;
    if (i < 3 * E * E) {
        int n = i >> 10;            // 0..3071
        int e = i & 1023;
        int wh = n >> 10;           // 0=q 1=k 2=v
        int hd = n & 1023;
        int h = hd >> 6, d = hd & 63;
        const float* W = (wh == 0) ? Wq : (wh == 1) ? Wk : Wv;
        g_Wqkv[i] = __float2half_rn(W[(h * E + e) * Dh + d]);
    }
    if (i < 3 * E) {
        const float* bs = (i < E) ? bq : (i < 2 * E) ? bk : bv;
        g_bqkv[i] = bs[i % E];
    }
}

// out[n*K + k] = fp16(in[k*N + n])
__global__ void transpose_kernel(const float* __restrict__ in, __half* __restrict__ out,
                                 int K, int N) {
    __shared__ float t[32][33];
    int k0 = blockIdx.x * 32, n0 = blockIdx.y * 32;
    int x = threadIdx.x, y = threadIdx.y;     // 32 x 8
    #pragma unroll
    for (int i = 0; i < 32; i += 8)
        t[y + i][x] = in[(size_t)(k0 + y + i) * N + n0 + x];
    __syncthreads();
    #pragma unroll
    for (int i = 0; i < 32; i += 8)
        out[(size_t)(n0 + y + i) * K + k0 + x] = __float2half_rn(t[x][y + i]);
}

// ---------------- layernorm (fp16 output) ----------------
__global__ void ln_kernel(const float* __restrict__ x, const float* __restrict__ g,
                          const float* __restrict__ b, __half* __restrict__ out) {
    int row = blockIdx.x;
    int tid = threadIdx.x;
    const float4 v = ((const float4*)(x + (size_t)row * E))[tid];
    float s  = v.x + v.y + v.z + v.w;
    float ss = v.x * v.x + v.y * v.y + v.z * v.z + v.w * v.w;
    #pragma unroll
    for (int o = 16; o; o >>= 1) {
        s  += __shfl_xor_sync(0xffffffffu, s,  o);
        ss += __shfl_xor_sync(0xffffffffu, ss, o);
    }
    __shared__ float sm[8], sm2[8];
    if ((tid & 31) == 0) { sm[tid >> 5] = s; sm2[tid >> 5] = ss; }
    __syncthreads();
    float tot = 0.f, tot2 = 0.f;
    #pragma unroll
    for (int i = 0; i < 8; i++) { tot += sm[i]; tot2 += sm2[i]; }
    float mean = tot * (1.0f / E);
    float var  = tot2 * (1.0f / E) - mean * mean;
    float inv  = rsqrtf(var + EPS);
    const float4 gg = ((const float4*)g)[tid];
    const float4 bb = ((const float4*)b)[tid];
    __half2* orow = (__half2*)(out + (size_t)row * E);
    orow[2 * tid]     = __floats2half2_rn((v.x - mean) * inv * gg.x + bb.x,
                                          (v.y - mean) * inv * gg.y + bb.y);
    orow[2 * tid + 1] = __floats2half2_rn((v.z - mean) * inv * gg.z + bb.z,
                                          (v.w - mean) * inv * gg.w + bb.w);
}

// ---------------- fp16 warp-MMA GEMM core macros ----------------
#define LDH 72
#define TILE_H (128 * LDH * 2)          // 18432 bytes per tile
#define STAGE_H (2 * TILE_H)            // 36864
#define GEMMH_SMEM (3 * STAGE_H)        // 110592 -> 2 CTAs/SM

// generic GEMM: C = A[M,K] @ Bt[N,K]^T (+bias)(+relu)(+res)
template<bool RELU, bool OUT_HALF>
__global__ __launch_bounds__(256, 2)
void gemm_h(const __half* __restrict__ A, const __half* __restrict__ Bt,
            const float* __restrict__ bias, const float* __restrict__ res,
            void* __restrict__ Cv, int M, int N, int K) {
    extern __shared__ char smem[];
    uint32_t sb = smem_u32(smem);
    int tid = threadIdx.x;
    int lane = tid & 31, wid = tid >> 5;
    int warp_m = wid & 3, warp_n = wid >> 2;
    int n0 = blockIdx.x * 128, m0 = blockIdx.y * 128;

    const __half* Abase = A  + (size_t)m0 * K;
    const __half* Bbase = Bt + (size_t)n0 * K;
    int NC = K >> 6;

    int lt = lane >> 3, lr = lane & 7;
    uint32_t aoff[2], boff[4];
    #pragma unroll
    for (int mt = 0; mt < 2; mt++)
        aoff[mt] = ((warp_m * 32 + mt * 16 + (lt & 1) * 8 + lr) * 36 + (lt >> 1) * 4) * 4;
    #pragma unroll
    for (int nt2 = 0; nt2 < 4; nt2++)
        boff[nt2] = TILE_H + ((warp_n * 64 + nt2 * 16 + (lt & 1) * 8 + lr) * 36 + (lt >> 1) * 4) * 4;

    #pragma unroll
    for (int st = 0; st < 2; st++) {
        uint32_t bufo = st * STAGE_H;
        int koff = st * 64;
        #pragma unroll
        for (int i = 0; i < 4; i++) {
            int idx = tid + i * 256;
            int row = idx >> 3, seg = idx & 7;
            CP_ASYNC16(sb + bufo + row * 144 + seg * 16,
                       Abase + (size_t)row * K + koff + seg * 8);
        }
        #pragma unroll
        for (int i = 0; i < 4; i++) {
            int idx = tid + i * 256;
            int row = idx >> 3, seg = idx & 7;
            CP_ASYNC16(sb + bufo + TILE_H + row * 144 + seg * 16,
                       Bbase + (size_t)row * K + koff + seg * 8);
        }
        CP_COMMIT();
    }
    CP_WAIT1();
    __syncthreads();

    float acc[2][8][4] = {};
    int cb = 0, pb = 2;
    int r = lane >> 2, cc = lane & 3;

    for (int c = 0; c < NC; c++) {
        if (c + 2 < NC) {
            uint32_t bufo = pb * STAGE_H;
            const __half* as = Abase + (c + 2) * 64;
            const __half* bs = Bbase + (c + 2) * 64;
            #pragma unroll
            for (int i = 0; i < 4; i++) {
                int idx = tid + i * 256;
                int row = idx >> 3, seg = idx & 7;
                CP_ASYNC16(sb + bufo + row * 144 + seg * 16,
                           as + (size_t)row * K + seg * 8);
            }
            #pragma unroll
            for (int i = 0; i < 4; i++) {
                int idx = tid + i * 256;
                int row = idx >> 3, seg = idx & 7;
                CP_ASYNC16(sb + bufo + TILE_H + row * 144 + seg * 16,
                           bs + (size_t)row * K + seg * 8);
            }
        }
        CP_COMMIT();

        uint32_t stage = sb + cb * STAGE_H;
        #pragma unroll
        for (int kk = 0; kk < 4; kk++) {
            uint32_t koff = kk * 32;
            uint32_t afr[2][4];
            LDMX4(afr[0][0], afr[0][1], afr[0][2], afr[0][3], stage + aoff[0] + koff);
            LDMX4(afr[1][0], afr[1][1], afr[1][2], afr[1][3], stage + aoff[1] + koff);
            #pragma unroll
            for (int nt2 = 0; nt2 < 4; nt2++) {
                uint32_t bfr[4];
                LDMX4(bfr[0], bfr[1], bfr[2], bfr[3], stage + boff[nt2] + koff);
                mma_f16(acc[0][2 * nt2    ], afr[0], bfr[0], bfr[2]);
                mma_f16(acc[1][2 * nt2    ], afr[1], bfr[0], bfr[2]);
                mma_f16(acc[0][2 * nt2 + 1], afr[0], bfr[1], bfr[3]);
                mma_f16(acc[1][2 * nt2 + 1], afr[1], bfr[1], bfr[3]);
            }
        }
        CP_WAIT1();
        __syncthreads();
        cb = (cb + 1 == 3) ? 0 : cb + 1;
        pb = (pb + 1 == 3) ? 0 : pb + 1;
    }

    #pragma unroll
    for (int mt = 0; mt < 2; mt++) {
        #pragma unroll
        for (int nt = 0; nt < 8; nt++) {
            int col = n0 + warp_n * 64 + nt * 8 + cc * 2;
            float2 bv = *(const float2*)&bias[col];
            #pragma unroll
            for (int rr = 0; rr < 2; rr++) {
                int row = m0 + warp_m * 32 + mt * 16 + r + rr * 8;
                float vx = acc[mt][nt][rr * 2 + 0] + bv.x;
                float vy = acc[mt][nt][rr * 2 + 1] + bv.y;
                if (RELU) { vx = fmaxf(vx, 0.f); vy = fmaxf(vy, 0.f); }
                if (res) {
                    float2 rv = *(const float2*)&res[(size_t)row * N + col];
                    vx += rv.x; vy += rv.y;
                }
                if (OUT_HALF) {
                    *(uint32_t*)&((__half*)Cv)[(size_t)row * N + col] = f22h2(vx, vy);
                } else {
                    float2 v = { vx, vy };
                    *(float2*)&((float*)Cv)[(size_t)row * N + col] = v;
                }
            }
        }
    }
}

// QKV GEMM: same mainloop, epilogue splits by region: Q -> qhi/qlo fp16, K -> fp32, V -> fp16
__global__ __launch_bounds__(256, 2)
void gemm_qkv(const __half* __restrict__ A, const __half* __restrict__ Bt,
              const float* __restrict__ bias,
              __half* __restrict__ qhi, __half* __restrict__ qlo,
              float* __restrict__ kf, __half* __restrict__ vf) {
    const int N = 3 * E, K = E;
    extern __shared__ char smem[];
    uint32_t sb = smem_u32(smem);
    int tid = threadIdx.x;
    int lane = tid & 31, wid = tid >> 5;
    int warp_m = wid & 3, warp_n = wid >> 2;
    int n0 = blockIdx.x * 128, m0 = blockIdx.y * 128;

    const __half* Abase = A  + (size_t)m0 * K;
    const __half* Bbase = Bt + (size_t)n0 * K;
    int NC = K >> 6;

    int lt = lane >> 3, lr = lane & 7;
    uint32_t aoff[2], boff[4];
    #pragma unroll
    for (int mt = 0; mt < 2; mt++)
        aoff[mt] = ((warp_m * 32 + mt * 16 + (lt & 1) * 8 + lr) * 36 + (lt >> 1) * 4) * 4;
    #pragma unroll
    for (int nt2 = 0; nt2 < 4; nt2++)
        boff[nt2] = TILE_H + ((warp_n * 64 + nt2 * 16 + (lt & 1) * 8 + lr) * 36 + (lt >> 1) * 4) * 4;

    #pragma unroll
    for (int st = 0; st < 2; st++) {
        uint32_t bufo = st * STAGE_H;
        int koff = st * 64;
        #pragma unroll
        for (int i = 0; i < 4; i++) {
            int idx = tid + i * 256;
            int row = idx >> 3, seg = idx & 7;
            CP_ASYNC16(sb + bufo + row * 144 + seg * 16,
                       Abase + (size_t)row * K + koff + seg * 8);
        }
        #pragma unroll
        for (int i = 0; i < 4; i++) {
            int idx = tid + i * 256;
            int row = idx >> 3, seg = idx & 7;
            CP_ASYNC16(sb + bufo + TILE_H + row * 144 + seg * 16,
                       Bbase + (size_t)row * K + koff + seg * 8);
        }
        CP_COMMIT();
    }
    CP_WAIT1();
    __syncthreads();

    float acc[2][8][4] = {};
    int cb = 0, pb = 2;
    int r = lane >> 2, cc = lane & 3;

    for (int c = 0; c < NC; c++) {
        if (c + 2 < NC) {
            uint32_t bufo = pb * STAGE_H;
            const __half* as = Abase + (c + 2) * 64;
            const __half* bs = Bbase + (c + 2) * 64;
            #pragma unroll
            for (int i = 0; i < 4; i++) {
                int idx = tid + i * 256;
                int row = idx >> 3, seg = idx & 7;
                CP_ASYNC16(sb + bufo + row * 144 + seg * 16,
                           as + (size_t)row * K + seg * 8);
            }
            #pragma unroll
            for (int i = 0; i < 4; i++) {
                int idx = tid + i * 256;
                int row = idx >> 3, seg = idx & 7;
                CP_ASYNC16(sb + bufo + TILE_H + row * 144 + seg * 16,
                           bs + (size_t)row * K + seg * 8);
            }
        }
        CP_COMMIT();

        uint32_t stage = sb + cb * STAGE_H;
        #pragma unroll
        for (int kk = 0; kk < 4; kk++) {
            uint32_t koff = kk * 32;
            uint32_t afr[2][4];
            LDMX4(afr[0][0], afr[0][1], afr[0][2], afr[0][3], stage + aoff[0] + koff);
            LDMX4(afr[1][0], afr[1][1], afr[1][2], afr[1][3], stage + aoff[1] + koff);
            #pragma unroll
            for (int nt2 = 0; nt2 < 4; nt2++) {
                uint32_t bfr[4];
                LDMX4(bfr[0], bfr[1], bfr[2], bfr[3], stage + boff[nt2] + koff);
                mma_f16(acc[0][2 * nt2    ], afr[0], bfr[0], bfr[2]);
                mma_f16(acc[1][2 * nt2    ], afr[1], bfr[0], bfr[2]);
                mma_f16(acc[0][2 * nt2 + 1], afr[0], bfr[1], bfr[3]);
                mma_f16(acc[1][2 * nt2 + 1], afr[1], bfr[1], bfr[3]);
            }
        }
        CP_WAIT1();
        __syncthreads();
        cb = (cb + 1 == 3) ? 0 : cb + 1;
        pb = (pb + 1 == 3) ? 0 : pb + 1;
    }

    // epilogue: region 0 = Q (hi/lo fp16), 1 = K (fp32), 2 = V (fp16)
    int region = n0 >> 10;
    #pragma unroll
    for (int mt = 0; mt < 2; mt++) {
        #pragma unroll
        for (int nt = 0; nt < 8; nt++) {
            int col = n0 + warp_n * 64 + nt * 8 + cc * 2;
            float2 bv = *(const float2*)&bias[col];
            int cr = col - region * E;
            #pragma unroll
            for (int rr = 0; rr < 2; rr++) {
                int row = m0 + warp_m * 32 + mt * 16 + r + rr * 8;
                float vx = acc[mt][nt][rr * 2 + 0] + bv.x;
                float vy = acc[mt][nt][rr * 2 + 1] + bv.y;
                size_t off = (size_t)row * E + cr;
                if (region == 1) {
                    float2 v = { vx, vy };
                    *(float2*)&kf[off] = v;
                } else if (region == 2) {
                    *(uint32_t*)&vf[off] = f22h2(vx, vy);
                } else {
                    __half hx = __float2half_rn(vx), hy = __float2half_rn(vy);
                    __half2 hh2; hh2.x = hx; hh2.y = hy;
                    *(__half2*)&qhi[off] = hh2;
                    *(uint32_t*)&qlo[off] = f22h2(vx - __half2float(hx),
                                                  vy - __half2float(hy));
                }
            }
        }
    }
}

// ---------------- fp16 MMA flash attention (rows = keys, softmax over queries) --
// CTA: 128 key rows, 8 warps. Q arrives pre-split (qhi/qlo fp16), V fp16.
// V B-frags via ldmatrix.trans (no smem transpose). Single __syncthreads per tile.
// smem bytes: QHI 2x9216 | QLO 2x9216 | VH 2x9216 | K fp32 128x68x4 (P reuses it)
#define AQHI_B 0
#define AQLO_B 18432
#define AVH_B  36864
#define AKF_B  55296
#define ATT_SMEM (AKF_B + 128 * 68 * 4)   // 90112 bytes -> 2 CTAs/SM

__global__ __launch_bounds__(256)
void attn_mma_kernel(const __half* __restrict__ qhi_g, const __half* __restrict__ qlo_g,
                     const float* __restrict__ k_g, const __half* __restrict__ v_g,
                     __half* __restrict__ o_out) {
    extern __shared__ float smf[];
    uint32_t sb = smem_u32(smf);
    uint32_t* smu = (uint32_t*)smf;

    int hb = blockIdx.y;
    int hh = hb >> 1, b = hb & 1;
    int s0 = blockIdx.x * 128;
    int tid = threadIdx.x, lane = tid & 31, wid = tid >> 5;
    int r = lane >> 2, cc = lane & 3;
    int rb = wid * 16 + r;

    // ldmatrix per-thread byte offsets
    int lt = lane >> 3, lr = lane & 7;
    uint32_t qhio[4], qloo[4], vofft[4], poff;
    {
        uint32_t rowsel = (lt & 1) * 8 + lr;
        uint32_t wordsel = (lt >> 1) * 4;
        #pragma unroll
        for (int nt2 = 0; nt2 < 4; nt2++) {
            uint32_t ro = ((nt2 * 16 + rowsel) * 36 + wordsel) * 4;   // B frags (n-rows)
            qhio[nt2] = AQHI_B + ro;
            qloo[nt2] = AQLO_B + ro;
            // V trans: rows = t (k dim), col bytes = d offset
            vofft[nt2] = AVH_B + rowsel * 144 + nt2 * 32 + (lt >> 1) * 16;
        }
        poff = AKF_B + ((wid * 16 + rowsel) * 36 + wordsel) * 4;
    }

    size_t tok0 = (size_t)(b * Ss);
    const float*  kbase = k_g   + (tok0 + s0) * E + hh * 64;
    const __half* qh_b  = qhi_g + tok0 * E + hh * 64;
    const __half* ql_b  = qlo_g + tok0 * E + hh * 64;
    const __half* v_b   = v_g   + tok0 * E + hh * 64;

    // K tile [128 x 64] fp32 (group 0)
    #pragma unroll
    for (int i = 0; i < 8; i++) {
        int idx = tid + i * 256;               // 0..2047
        int row = idx >> 4, seg = idx & 15;
        CP_ASYNC16(sb + AKF_B + row * 272 + seg * 16,
                   kbase + (size_t)row * E + seg * 4);
    }
    CP_COMMIT();
    // Qhi/Qlo/V tile 0 -> buffer 0 (group 1): each 64 rows x 8 segs = 512 slots
    #pragma unroll
    for (int i = 0; i < 2; i++) {
        int idx = tid + i * 256;               // 0..511
        int row = idx >> 3, seg = idx & 7;
        uint32_t doff = row * 144 + seg * 16;
        const size_t goff = (size_t)row * E + seg * 8;
        CP_ASYNC16(sb + AQHI_B + doff, qh_b + goff);
        CP_ASYNC16(sb + AQLO_B + doff, ql_b + goff);
        CP_ASYNC16(sb + AVH_B  + doff, v_b  + goff);
    }
    CP_COMMIT();
    CP_WAIT1();              // K resident
    __syncthreads();

    // K fragments hi/lo fp16 in registers: m16 x k64 (4 k16-steps)
    uint32_t kfh[4][4], kfl[4][4];
    #pragma unroll
    for (int kk = 0; kk < 4; kk++) {
        float2 kv[4];
        const float* kfp = smf + AKF_B / 4;
        kv[0] = *(float2*)&kfp[(rb    ) * 68 + kk * 16 + 2 * cc];
        kv[1] = *(float2*)&kfp[(rb + 8) * 68 + kk * 16 + 2 * cc];
        kv[2] = *(float2*)&kfp[(rb    ) * 68 + kk * 16 + 2 * cc + 8];
        kv[3] = *(float2*)&kfp[(rb + 8) * 68 + kk * 16 + 2 * cc + 8];
        #pragma unroll
        for (int j = 0; j < 4; j++) {
            float hx = __half2float(__float2half_rn(kv[j].x));
            float hy = __half2float(__float2half_rn(kv[j].y));
            kfh[kk][j] = f22h2(hx, hy);
            kfl[kk][j] = f22h2(kv[j].x - hx, kv[j].y - hy);
        }
    }
    __syncthreads();          // K region now reusable as P

    float mrow0 = -1e30f, mrow1 = -1e30f, lrow0 = 0.f, lrow1 = 0.f;
    float o[8][4] = {};

    for (int t0 = 0; t0 < Ss; t0 += 64) {
        int buf = (t0 >> 6) & 1;
        uint32_t bufo = buf * 9216;
        if (t0 + 64 < Ss) {
            uint32_t nbo = (buf ^ 1) * 9216;
            size_t src0 = (size_t)(t0 + 64) * E;
            #pragma unroll
            for (int i = 0; i < 2; i++) {
                int idx = tid + i * 256;
                int row = idx >> 3, seg = idx & 7;
                uint32_t doff = nbo + row * 144 + seg * 16;
                const size_t goff = src0 + (size_t)row * E + seg * 8;
                CP_ASYNC16(sb + AQHI_B + doff, qh_b + goff);
                CP_ASYNC16(sb + AQLO_B + doff, ql_b + goff);
                CP_ASYNC16(sb + AVH_B  + doff, v_b  + goff);
            }
            CP_COMMIT();
        }

        // S = K x Q^T : split-fp16 (3 MMAs per k16-step), Q frags via ldmatrix
        float s[8][4] = {};
        #pragma unroll
        for (int kk = 0; kk < 4; kk++) {
            uint32_t koff = bufo + kk * 32;
            #pragma unroll
            for (int nt2 = 0; nt2 < 4; nt2++) {
                uint32_t qh[4], ql[4];
                LDMX4(qh[0], qh[1], qh[2], qh[3], sb + qhio[nt2] + koff);
                LDMX4(ql[0], ql[1], ql[2], ql[3], sb + qloo[nt2] + koff);
                mma_f16(s[2 * nt2    ], kfh[kk], qh[0], qh[2]);
                mma_f16(s[2 * nt2    ], kfh[kk], ql[0], ql[2]);
                mma_f16(s[2 * nt2    ], kfl[kk], qh[0], qh[2]);
                mma_f16(s[2 * nt2 + 1], kfh[kk], qh[1], qh[3]);
                mma_f16(s[2 * nt2 + 1], kfh[kk], ql[1], ql[3]);
                mma_f16(s[2 * nt2 + 1], kfl[kk], qh[1], qh[3]);
            }
        }

        // online softmax over t (rows in-warp: quad shfl reduce)
        float mx0 = -1e30f, mx1 = -1e30f;
        #pragma unroll
        for (int nt = 0; nt < 8; nt++) {
            mx0 = fmaxf(mx0, fmaxf(s[nt][0], s[nt][1]));
            mx1 = fmaxf(mx1, fmaxf(s[nt][2], s[nt][3]));
        }
        mx0 = fmaxf(mx0, __shfl_xor_sync(0xffffffffu, mx0, 1));
        mx0 = fmaxf(mx0, __shfl_xor_sync(0xffffffffu, mx0, 2));
        mx1 = fmaxf(mx1, __shfl_xor_sync(0xffffffffu, mx1, 1));
        mx1 = fmaxf(mx1, __shfl_xor_sync(0xffffffffu, mx1, 2));
        float mn0 = fmaxf(mrow0, mx0), mn1 = fmaxf(mrow1, mx1);
        float a0 = __expf(mrow0 - mn0), a1 = __expf(mrow1 - mn1);
        mrow0 = mn0; mrow1 = mn1;

        float ps0 = 0.f, ps1 = 0.f;
        #pragma unroll
        for (int nt = 0; nt < 8; nt++) {
            float p0 = __expf(s[nt][0] - mn0);
            float p1 = __expf(s[nt][1] - mn0);
            float p2 = __expf(s[nt][2] - mn1);
            float p3 = __expf(s[nt][3] - mn1);
            ps0 += p0 + p1;
            ps1 += p2 + p3;
            smu[AKF_B / 4 + (rb    ) * 36 + nt * 4 + cc] = f22h2(p0, p1);
            smu[AKF_B / 4 + (rb + 8) * 36 + nt * 4 + cc] = f22h2(p2, p3);
        }
        ps0 += __shfl_xor_sync(0xffffffffu, ps0, 1);
        ps0 += __shfl_xor_sync(0xffffffffu, ps0, 2);
        ps1 += __shfl_xor_sync(0xffffffffu, ps1, 1);
        ps1 += __shfl_xor_sync(0xffffffffu, ps1, 2);
        lrow0 = lrow0 * a0 + ps0;
        lrow1 = lrow1 * a1 + ps1;
        #pragma unroll
        for (int nt = 0; nt < 8; nt++) {
            o[nt][0] *= a0; o[nt][1] *= a0;
            o[nt][2] *= a1; o[nt][3] *= a1;
        }
        __syncwarp();   // this warp's P rows visible (warp-private rows)

        // O += P x V : P A-frags via ldmatrix, V B-frags via ldmatrix.trans
        #pragma unroll
        for (int kk = 0; kk < 4; kk++) {
            uint32_t pa[4];
            LDMX4(pa[0], pa[1], pa[2], pa[3], sb + poff + kk * 32);
            uint32_t vko = bufo + kk * 2304;       // 16 t-rows * 144B
            #pragma unroll
            for (int nt2 = 0; nt2 < 4; nt2++) {
                uint32_t vf[4];
                LDMX4T(vf[0], vf[1], vf[2], vf[3], sb + vofft[nt2] + vko);
                mma_f16(o[2 * nt2    ], pa, vf[0], vf[1]);
                mma_f16(o[2 * nt2 + 1], pa, vf[2], vf[3]);
            }
        }
        CP_WAIT0();
        __syncthreads();    // next tiles resident; all warps done with buf
    }

    float i0 = 1.f / lrow0, i1 = 1.f / lrow1;
    uint32_t* orow0 = (uint32_t*)(o_out + (size_t)(b * Ss + s0 + rb) * E + hh * 64);
    uint32_t* orow1 = (uint32_t*)(o_out + (size_t)(b * Ss + s0 + rb + 8) * E + hh * 64);
    #pragma unroll
    for (int nt = 0; nt < 8; nt++) {
        orow0[nt * 4 + cc] = f22h2(o[nt][0] * i0, o[nt][1] * i0);
        orow1[nt * 4 + cc] = f22h2(o[nt][2] * i1, o[nt][3] * i1);
    }
}

// ---------------- host launch ----------------
extern "C" void kernel_launch(void* const* d_in, const int* in_sizes, int n_in,
                              void* d_out, int out_size) {
    const float* x     = (const float*)d_in[0];
    const float* Wq    = (const float*)d_in[1];
    const float* bq    = (const float*)d_in[2];
    const float* Wk    = (const float*)d_in[3];
    const float* bk    = (const float*)d_in[4];
    const float* Wv    = (const float*)d_in[5];
    const float* bv    = (const float*)d_in[6];
    const float* Wo    = (const float*)d_in[7];
    const float* bo    = (const float*)d_in[8];
    const float* ln1_g = (const float*)d_in[9];
    const float* ln1_b = (const float*)d_in[10];
    const float* ln2_g = (const float*)d_in[11];
    const float* ln2_b = (const float*)d_in[12];
    const float* W1    = (const float*)d_in[13];
    const float* b1    = (const float*)d_in[14];
    const float* W2    = (const float*)d_in[15];
    const float* b2    = (const float*)d_in[16];
    float* out = (float*)d_out;

    __half *p_h, *p_qhi, *p_qlo, *p_v, *p_Wqkv, *p_WoT, *p_W1T, *p_W2T, *p_o, *p_h2, *p_m1;
    float *p_k, *p_bqkv, *p_x1;
    cudaGetSymbolAddress((void**)&p_h,    g_h);
    cudaGetSymbolAddress((void**)&p_qhi,  g_qhi);
    cudaGetSymbolAddress((void**)&p_qlo,  g_qlo);
    cudaGetSymbolAddress((void**)&p_k,    g_k);
    cudaGetSymbolAddress((void**)&p_v,    g_v);
    cudaGetSymbolAddress((void**)&p_Wqkv, g_Wqkv);
    cudaGetSymbolAddress((void**)&p_bqkv, g_bqkv);
    cudaGetSymbolAddress((void**)&p_WoT,  g_WoT);
    cudaGetSymbolAddress((void**)&p_W1T,  g_W1T);
    cudaGetSymbolAddress((void**)&p_W2T,  g_W2T);
    cudaGetSymbolAddress((void**)&p_o,    g_o);
    cudaGetSymbolAddress((void**)&p_x1,   g_x1);
    cudaGetSymbolAddress((void**)&p_h2,   g_h2);
    cudaGetSymbolAddress((void**)&p_m1,   g_m1);

    cudaFuncSetAttribute(gemm_h<false, false>, cudaFuncAttributeMaxDynamicSharedMemorySize, GEMMH_SMEM);
    cudaFuncSetAttribute(gemm_h<true,  true>,  cudaFuncAttributeMaxDynamicSharedMemorySize, GEMMH_SMEM);
    cudaFuncSetAttribute(gemm_qkv,             cudaFuncAttributeMaxDynamicSharedMemorySize, GEMMH_SMEM);
    cudaFuncSetAttribute(attn_mma_kernel,      cudaFuncAttributeMaxDynamicSharedMemorySize, ATT_SMEM);

    // 1. pack fused QKV weight (transposed, fp16) + bias; transpose Wo, W1, W2 (fp16)
    pack_qkv_kernel<<<(3 * E * E + 255) / 256, 256>>>(Wq, Wk, Wv, bq, bk, bv);
    transpose_kernel<<<dim3(E / 32, E / 32),  dim3(32, 8)>>>(Wo, p_WoT, E, E);
    transpose_kernel<<<dim3(E / 32, Ff / 32), dim3(32, 8)>>>(W1, p_W1T, E, Ff);
    transpose_kernel<<<dim3(Ff / 32, E / 32), dim3(32, 8)>>>(W2, p_W2T, Ff, E);

    // 2. LN1 (fp16 out)
    ln_kernel<<<NT, 256>>>(x, ln1_g, ln1_b, p_h);

    // 3. fused QKV projection: epilogue pre-splits Q (hi/lo fp16), K fp32, V fp16
    gemm_qkv<<<dim3(3 * E / 128, NT / 128), 256, GEMMH_SMEM>>>(p_h, p_Wqkv, p_bqkv, p_qhi, p_qlo, p_k, p_v);

    // 4. attention (split-fp16 S, fp16 PV) -> fp16 o
    attn_mma_kernel<<<dim3(Ss / 128, H * Bb), 256, ATT_SMEM>>>(p_qhi, p_qlo, p_k, p_v, p_o);

    // 5. output projection + residual (fp32 out)
    gemm_h<false, false><<<dim3(E / 128, NT / 128), 256, GEMMH_SMEM>>>(p_o, p_WoT, bo, x, p_x1, NT, E, E);

    // 6. LN2 (fp16 out)
    ln_kernel<<<NT, 256>>>(p_x1, ln2_g, ln2_b, p_h2);

    // 7. MLP up + ReLU (fp16 out -> feeds MLP down as A)
    gemm_h<true, true><<<dim3(Ff / 128, NT / 128), 256, GEMMH_SMEM>>>(p_h2, p_W1T, b1, nullptr, p_m1, NT, Ff, E);

    // 8. MLP down + residual -> fp32 output
    gemm_h<false, false><<<dim3(E / 128, NT / 128), 256, GEMMH_SMEM>>>(p_m1, p_W2T, b2, p_x1, out, NT, E, Ff);
}

// round 15
// speedup vs baseline: 1.1871x; 1.1013x over previous
#include <cuda_runtime.h>
#include <cuda_fp16.h>
#include <cstdint>
#include <math.h>

#define E    1024
#define Dh   64
#define H    16
#define Ff   4096
#define Bb   2
#define Ss   2048
#define NT   (Bb*Ss)     // 4096 tokens
#define EPS  1e-5f

// ---------------- scratch (static device memory; no allocation) ----------------
__device__ __half g_h   [NT * E];        // LN1 output (fp16)
__device__ __half g_qhi [NT * E];        // Q hi fp16
__device__ __half g_qlo [NT * E];        // Q lo fp16 (residual)
__device__ float  g_k   [NT * E];        // K fp32
__device__ __half g_v   [NT * E];        // V fp16
__device__ __half g_Wqkv[3 * E * E];     // packed W_qkv^T : [3072, 1024] (N,K) fp16
__device__ float  g_bqkv[3 * E];
__device__ __half g_WoT [E * E];         // Wo^T  fp16
__device__ __half g_W1T [Ff * E];        // W1^T  fp16
__device__ __half g_W2T [E * Ff];        // W2^T  fp16
__device__ __half g_o   [NT * E];        // attention out (fp16)
__device__ float  g_x1  [NT * E];        // after first residual (fp32)
__device__ __half g_h2  [NT * E];        // LN2 output (fp16)
__device__ __half g_m1  [NT * Ff];       // relu(h2 @ W1 + b1) (fp16)

// ======================= helpers =======================
__device__ __forceinline__ uint32_t smem_u32(const void* p) {
    uint32_t a;
    asm("{ .reg .u64 t; cvta.to.shared.u64 t, %1; cvt.u32.u64 %0, t; }" : "=r"(a) : "l"(p));
    return a;
}
__device__ __forceinline__ uint32_t f22h2(float a, float b) {
    __half2 h = __floats2half2_rn(a, b);
    return *(uint32_t*)&h;
}
#define CP_ASYNC16(dst, src) \
    asm volatile("cp.async.cg.shared.global [%0], [%1], 16;" :: "r"((uint32_t)(dst)), "l"(src))
#define CP_COMMIT() asm volatile("cp.async.commit_group;" ::: "memory")
#define CP_WAIT0()  asm volatile("cp.async.wait_group 0;" ::: "memory")
#define CP_WAIT1()  asm volatile("cp.async.wait_group 1;" ::: "memory")

#define LDMX4(r0, r1, r2, r3, addr) \
    asm volatile("ldmatrix.sync.aligned.m8n8.x4.shared.b16 {%0,%1,%2,%3}, [%4];" \
        : "=r"(r0), "=r"(r1), "=r"(r2), "=r"(r3) : "r"(addr))
#define LDMX4T(r0, r1, r2, r3, addr) \
    asm volatile("ldmatrix.sync.aligned.m8n8.x4.trans.shared.b16 {%0,%1,%2,%3}, [%4];" \
        : "=r"(r0), "=r"(r1), "=r"(r2), "=r"(r3) : "r"(addr))

// m16n8k16 fp16 mma: D(f32) += A(f16) * B(f16)
__device__ __forceinline__ void mma_f16(float* c, const uint32_t* a, uint32_t b0, uint32_t b1) {
    asm volatile(
        "mma.sync.aligned.m16n8k16.row.col.f32.f16.f16.f32 "
        "{%0,%1,%2,%3}, {%4,%5,%6,%7}, {%8,%9}, {%0,%1,%2,%3};"
        : "+f"(c[0]), "+f"(c[1]), "+f"(c[2]), "+f"(c[3])
        : "r"(a[0]), "r"(a[1]), "r"(a[2]), "r"(a[3]), "r"(b0), "r"(b1));
}

// ---------------- weight packing (fp16) ----------------
__global__ void pack_qkv_kernel(const float* __restrict__ Wq, const float* __restrict__ Wk,
                                const float* __restrict__ Wv, const float* __restrict__ bq,
                                const float* __restrict__ bk, const float* __restrict__ bv) {
    int i = blockIdx.x * blockDim.x + threadIdx.x;
    if (i < 3 * E * E) {
        int n = i >> 10;            // 0..3071
        int e = i & 1023;
        int wh = n >> 10;           // 0=q 1=k 2=v
        int hd = n & 1023;
        int h = hd >> 6, d = hd & 63;
        const float* W = (wh == 0) ? Wq : (wh == 1) ? Wk : Wv;
        g_Wqkv[i] = __float2half_rn(W[(h * E + e) * Dh + d]);
    }
    if (i < 3 * E) {
        const float* bs = (i < E) ? bq : (i < 2 * E) ? bk : bv;
        g_bqkv[i] = bs[i % E];
    }
}

// out[n*K + k] = fp16(in[k*N + n])
__global__ void transpose_kernel(const float* __restrict__ in, __half* __restrict__ out,
                                 int K, int N) {
    __shared__ float t[32][33];
    int k0 = blockIdx.x * 32, n0 = blockIdx.y * 32;
    int x = threadIdx.x, y = threadIdx.y;     // 32 x 8
    #pragma unroll
    for (int i = 0; i < 32; i += 8)
        t[y + i][x] = in[(size_t)(k0 + y + i) * N + n0 + x];
    __syncthreads();
    #pragma unroll
    for (int i = 0; i < 32; i += 8)
        out[(size_t)(n0 + y + i) * K + k0 + x] = __float2half_rn(t[x][y + i]);
}

// ---------------- layernorm (fp16 output) ----------------
__global__ void ln_kernel(const float* __restrict__ x, const float* __restrict__ g,
                          const float* __restrict__ b, __half* __restrict__ out) {
    int row = blockIdx.x;
    int tid = threadIdx.x;
    const float4 v = ((const float4*)(x + (size_t)row * E))[tid];
    float s  = v.x + v.y + v.z + v.w;
    float ss = v.x * v.x + v.y * v.y + v.z * v.z + v.w * v.w;
    #pragma unroll
    for (int o = 16; o; o >>= 1) {
        s  += __shfl_xor_sync(0xffffffffu, s,  o);
        ss += __shfl_xor_sync(0xffffffffu, ss, o);
    }
    __shared__ float sm[8], sm2[8];
    if ((tid & 31) == 0) { sm[tid >> 5] = s; sm2[tid >> 5] = ss; }
    __syncthreads();
    float tot = 0.f, tot2 = 0.f;
    #pragma unroll
    for (int i = 0; i < 8; i++) { tot += sm[i]; tot2 += sm2[i]; }
    float mean = tot * (1.0f / E);
    float var  = tot2 * (1.0f / E) - mean * mean;
    float inv  = rsqrtf(var + EPS);
    const float4 gg = ((const float4*)g)[tid];
    const float4 bb = ((const float4*)b)[tid];
    __half2* orow = (__half2*)(out + (size_t)row * E);
    orow[2 * tid]     = __floats2half2_rn((v.x - mean) * inv * gg.x + bb.x,
                                          (v.y - mean) * inv * gg.y + bb.y);
    orow[2 * tid + 1] = __floats2half2_rn((v.z - mean) * inv * gg.z + bb.z,
                                          (v.w - mean) * inv * gg.w + bb.w);
}

// ---------------- fp16 warp-MMA GEMM core macros ----------------
#define LDH 72
#define TILE_H (128 * LDH * 2)          // 18432 bytes per tile
#define STAGE_H (2 * TILE_H)            // 36864
#define GEMMH_SMEM (3 * STAGE_H)        // 110592 -> 2 CTAs/SM

// generic GEMM: C = A[M,K] @ Bt[N,K]^T (+bias)(+relu)(+res)
template<bool RELU, bool OUT_HALF>
__global__ __launch_bounds__(256, 2)
void gemm_h(const __half* __restrict__ A, const __half* __restrict__ Bt,
            const float* __restrict__ bias, const float* __restrict__ res,
            void* __restrict__ Cv, int M, int N, int K) {
    extern __shared__ char smem[];
    uint32_t sb = smem_u32(smem);
    int tid = threadIdx.x;
    int lane = tid & 31, wid = tid >> 5;
    int warp_m = wid & 3, warp_n = wid >> 2;
    int n0 = blockIdx.x * 128, m0 = blockIdx.y * 128;

    const __half* Abase = A  + (size_t)m0 * K;
    const __half* Bbase = Bt + (size_t)n0 * K;
    int NC = K >> 6;

    int lt = lane >> 3, lr = lane & 7;
    uint32_t aoff[2], boff[4];
    #pragma unroll
    for (int mt = 0; mt < 2; mt++)
        aoff[mt] = ((warp_m * 32 + mt * 16 + (lt & 1) * 8 + lr) * 36 + (lt >> 1) * 4) * 4;
    #pragma unroll
    for (int nt2 = 0; nt2 < 4; nt2++)
        boff[nt2] = TILE_H + ((warp_n * 64 + nt2 * 16 + (lt & 1) * 8 + lr) * 36 + (lt >> 1) * 4) * 4;

    #pragma unroll
    for (int st = 0; st < 2; st++) {
        uint32_t bufo = st * STAGE_H;
        int koff = st * 64;
        #pragma unroll
        for (int i = 0; i < 4; i++) {
            int idx = tid + i * 256;
            int row = idx >> 3, seg = idx & 7;
            CP_ASYNC16(sb + bufo + row * 144 + seg * 16,
                       Abase + (size_t)row * K + koff + seg * 8);
        }
        #pragma unroll
        for (int i = 0; i < 4; i++) {
            int idx = tid + i * 256;
            int row = idx >> 3, seg = idx & 7;
            CP_ASYNC16(sb + bufo + TILE_H + row * 144 + seg * 16,
                       Bbase + (size_t)row * K + koff + seg * 8);
        }
        CP_COMMIT();
    }
    CP_WAIT1();
    __syncthreads();

    float acc[2][8][4] = {};
    int cb = 0, pb = 2;
    int r = lane >> 2, cc = lane & 3;

    for (int c = 0; c < NC; c++) {
        if (c + 2 < NC) {
            uint32_t bufo = pb * STAGE_H;
            const __half* as = Abase + (c + 2) * 64;
            const __half* bs = Bbase + (c + 2) * 64;
            #pragma unroll
            for (int i = 0; i < 4; i++) {
                int idx = tid + i * 256;
                int row = idx >> 3, seg = idx & 7;
                CP_ASYNC16(sb + bufo + row * 144 + seg * 16,
                           as + (size_t)row * K + seg * 8);
            }
            #pragma unroll
            for (int i = 0; i < 4; i++) {
                int idx = tid + i * 256;
                int row = idx >> 3, seg = idx & 7;
                CP_ASYNC16(sb + bufo + TILE_H + row * 144 + seg * 16,
                           bs + (size_t)row * K + seg * 8);
            }
        }
        CP_COMMIT();

        uint32_t stage = sb + cb * STAGE_H;
        #pragma unroll
        for (int kk = 0; kk < 4; kk++) {
            uint32_t koff = kk * 32;
            uint32_t afr[2][4];
            LDMX4(afr[0][0], afr[0][1], afr[0][2], afr[0][3], stage + aoff[0] + koff);
            LDMX4(afr[1][0], afr[1][1], afr[1][2], afr[1][3], stage + aoff[1] + koff);
            #pragma unroll
            for (int nt2 = 0; nt2 < 4; nt2++) {
                uint32_t bfr[4];
                LDMX4(bfr[0], bfr[1], bfr[2], bfr[3], stage + boff[nt2] + koff);
                mma_f16(acc[0][2 * nt2    ], afr[0], bfr[0], bfr[2]);
                mma_f16(acc[1][2 * nt2    ], afr[1], bfr[0], bfr[2]);
                mma_f16(acc[0][2 * nt2 + 1], afr[0], bfr[1], bfr[3]);
                mma_f16(acc[1][2 * nt2 + 1], afr[1], bfr[1], bfr[3]);
            }
        }
        CP_WAIT1();
        __syncthreads();
        cb = (cb + 1 == 3) ? 0 : cb + 1;
        pb = (pb + 1 == 3) ? 0 : pb + 1;
    }

    #pragma unroll
    for (int mt = 0; mt < 2; mt++) {
        #pragma unroll
        for (int nt = 0; nt < 8; nt++) {
            int col = n0 + warp_n * 64 + nt * 8 + cc * 2;
            float2 bv = *(const float2*)&bias[col];
            #pragma unroll
            for (int rr = 0; rr < 2; rr++) {
                int row = m0 + warp_m * 32 + mt * 16 + r + rr * 8;
                float vx = acc[mt][nt][rr * 2 + 0] + bv.x;
                float vy = acc[mt][nt][rr * 2 + 1] + bv.y;
                if (RELU) { vx = fmaxf(vx, 0.f); vy = fmaxf(vy, 0.f); }
                if (res) {
                    float2 rv = *(const float2*)&res[(size_t)row * N + col];
                    vx += rv.x; vy += rv.y;
                }
                if (OUT_HALF) {
                    *(uint32_t*)&((__half*)Cv)[(size_t)row * N + col] = f22h2(vx, vy);
                } else {
                    float2 v = { vx, vy };
                    *(float2*)&((float*)Cv)[(size_t)row * N + col] = v;
                }
            }
        }
    }
}

// QKV GEMM: same mainloop, epilogue splits by region: Q -> qhi/qlo fp16, K -> fp32, V -> fp16
__global__ __launch_bounds__(256, 2)
void gemm_qkv(const __half* __restrict__ A, const __half* __restrict__ Bt,
              const float* __restrict__ bias,
              __half* __restrict__ qhi, __half* __restrict__ qlo,
              float* __restrict__ kf, __half* __restrict__ vf) {
    const int N = 3 * E, K = E;
    extern __shared__ char smem[];
    uint32_t sb = smem_u32(smem);
    int tid = threadIdx.x;
    int lane = tid & 31, wid = tid >> 5;
    int warp_m = wid & 3, warp_n = wid >> 2;
    int n0 = blockIdx.x * 128, m0 = blockIdx.y * 128;

    const __half* Abase = A  + (size_t)m0 * K;
    const __half* Bbase = Bt + (size_t)n0 * K;
    int NC = K >> 6;

    int lt = lane >> 3, lr = lane & 7;
    uint32_t aoff[2], boff[4];
    #pragma unroll
    for (int mt = 0; mt < 2; mt++)
        aoff[mt] = ((warp_m * 32 + mt * 16 + (lt & 1) * 8 + lr) * 36 + (lt >> 1) * 4) * 4;
    #pragma unroll
    for (int nt2 = 0; nt2 < 4; nt2++)
        boff[nt2] = TILE_H + ((warp_n * 64 + nt2 * 16 + (lt & 1) * 8 + lr) * 36 + (lt >> 1) * 4) * 4;

    #pragma unroll
    for (int st = 0; st < 2; st++) {
        uint32_t bufo = st * STAGE_H;
        int koff = st * 64;
        #pragma unroll
        for (int i = 0; i < 4; i++) {
            int idx = tid + i * 256;
            int row = idx >> 3, seg = idx & 7;
            CP_ASYNC16(sb + bufo + row * 144 + seg * 16,
                       Abase + (size_t)row * K + koff + seg * 8);
        }
        #pragma unroll
        for (int i = 0; i < 4; i++) {
            int idx = tid + i * 256;
            int row = idx >> 3, seg = idx & 7;
            CP_ASYNC16(sb + bufo + TILE_H + row * 144 + seg * 16,
                       Bbase + (size_t)row * K + koff + seg * 8);
        }
        CP_COMMIT();
    }
    CP_WAIT1();
    __syncthreads();

    float acc[2][8][4] = {};
    int cb = 0, pb = 2;
    int r = lane >> 2, cc = lane & 3;

    for (int c = 0; c < NC; c++) {
        if (c + 2 < NC) {
            uint32_t bufo = pb * STAGE_H;
            const __half* as = Abase + (c + 2) * 64;
            const __half* bs = Bbase + (c + 2) * 64;
            #pragma unroll
            for (int i = 0; i < 4; i++) {
                int idx = tid + i * 256;
                int row = idx >> 3, seg = idx & 7;
                CP_ASYNC16(sb + bufo + row * 144 + seg * 16,
                           as + (size_t)row * K + seg * 8);
            }
            #pragma unroll
            for (int i = 0; i < 4; i++) {
                int idx = tid + i * 256;
                int row = idx >> 3, seg = idx & 7;
                CP_ASYNC16(sb + bufo + TILE_H + row * 144 + seg * 16,
                           bs + (size_t)row * K + seg * 8);
            }
        }
        CP_COMMIT();

        uint32_t stage = sb + cb * STAGE_H;
        #pragma unroll
        for (int kk = 0; kk < 4; kk++) {
            uint32_t koff = kk * 32;
            uint32_t afr[2][4];
            LDMX4(afr[0][0], afr[0][1], afr[0][2], afr[0][3], stage + aoff[0] + koff);
            LDMX4(afr[1][0], afr[1][1], afr[1][2], afr[1][3], stage + aoff[1] + koff);
            #pragma unroll
            for (int nt2 = 0; nt2 < 4; nt2++) {
                uint32_t bfr[4];
                LDMX4(bfr[0], bfr[1], bfr[2], bfr[3], stage + boff[nt2] + koff);
                mma_f16(acc[0][2 * nt2    ], afr[0], bfr[0], bfr[2]);
                mma_f16(acc[1][2 * nt2    ], afr[1], bfr[0], bfr[2]);
                mma_f16(acc[0][2 * nt2 + 1], afr[0], bfr[1], bfr[3]);
                mma_f16(acc[1][2 * nt2 + 1], afr[1], bfr[1], bfr[3]);
            }
        }
        CP_WAIT1();
        __syncthreads();
        cb = (cb + 1 == 3) ? 0 : cb + 1;
        pb = (pb + 1 == 3) ? 0 : pb + 1;
    }

    // epilogue: region 0 = Q (hi/lo fp16), 1 = K (fp32), 2 = V (fp16)
    int region = n0 >> 10;
    #pragma unroll
    for (int mt = 0; mt < 2; mt++) {
        #pragma unroll
        for (int nt = 0; nt < 8; nt++) {
            int col = n0 + warp_n * 64 + nt * 8 + cc * 2;
            float2 bv = *(const float2*)&bias[col];
            int cr = col - region * E;
            #pragma unroll
            for (int rr = 0; rr < 2; rr++) {
                int row = m0 + warp_m * 32 + mt * 16 + r + rr * 8;
                float vx = acc[mt][nt][rr * 2 + 0] + bv.x;
                float vy = acc[mt][nt][rr * 2 + 1] + bv.y;
                size_t off = (size_t)row * E + cr;
                if (region == 1) {
                    float2 v = { vx, vy };
                    *(float2*)&kf[off] = v;
                } else if (region == 2) {
                    *(uint32_t*)&vf[off] = f22h2(vx, vy);
                } else {
                    __half hx = __float2half_rn(vx), hy = __float2half_rn(vy);
                    __half2 hh2; hh2.x = hx; hh2.y = hy;
                    *(__half2*)&qhi[off] = hh2;
                    *(uint32_t*)&qlo[off] = f22h2(vx - __half2float(hx),
                                                  vy - __half2float(hy));
                }
            }
        }
    }
}

// ---------------- fp16 MMA flash attention (rows = keys, softmax over queries) --
// CTA: 128 key rows, 8 warps. Q pre-split (qhi/qlo fp16), V fp16, K fp32->Khi regs.
// 2-term S: S = Khi*(Qhi+Qlo) (Klo term dropped; error ~2e-3 abs score noise).
#define AQHI_B 0
#define AQLO_B 18432
#define AVH_B  36864
#define AKF_B  55296
#define ATT_SMEM (AKF_B + 128 * 68 * 4)   // 90112 bytes -> 2 CTAs/SM

__global__ __launch_bounds__(256)
void attn_mma_kernel(const __half* __restrict__ qhi_g, const __half* __restrict__ qlo_g,
                     const float* __restrict__ k_g, const __half* __restrict__ v_g,
                     __half* __restrict__ o_out) {
    extern __shared__ float smf[];
    uint32_t sb = smem_u32(smf);
    uint32_t* smu = (uint32_t*)smf;

    int hb = blockIdx.y;
    int hh = hb >> 1, b = hb & 1;
    int s0 = blockIdx.x * 128;
    int tid = threadIdx.x, lane = tid & 31, wid = tid >> 5;
    int r = lane >> 2, cc = lane & 3;
    int rb = wid * 16 + r;

    // ldmatrix per-thread byte offsets
    int lt = lane >> 3, lr = lane & 7;
    uint32_t qhio[4], qloo[4], vofft[4], poff;
    {
        uint32_t rowsel = (lt & 1) * 8 + lr;
        uint32_t wordsel = (lt >> 1) * 4;
        #pragma unroll
        for (int nt2 = 0; nt2 < 4; nt2++) {
            uint32_t ro = ((nt2 * 16 + rowsel) * 36 + wordsel) * 4;   // B frags (n-rows)
            qhio[nt2] = AQHI_B + ro;
            qloo[nt2] = AQLO_B + ro;
            // V trans: rows = t (k dim), col bytes = d offset
            vofft[nt2] = AVH_B + rowsel * 144 + nt2 * 32 + (lt >> 1) * 16;
        }
        poff = AKF_B + ((wid * 16 + rowsel) * 36 + wordsel) * 4;
    }

    size_t tok0 = (size_t)(b * Ss);
    const float*  kbase = k_g   + (tok0 + s0) * E + hh * 64;
    const __half* qh_b  = qhi_g + tok0 * E + hh * 64;
    const __half* ql_b  = qlo_g + tok0 * E + hh * 64;
    const __half* v_b   = v_g   + tok0 * E + hh * 64;

    // K tile [128 x 64] fp32 (group 0)
    #pragma unroll
    for (int i = 0; i < 8; i++) {
        int idx = tid + i * 256;               // 0..2047
        int row = idx >> 4, seg = idx & 15;
        CP_ASYNC16(sb + AKF_B + row * 272 + seg * 16,
                   kbase + (size_t)row * E + seg * 4);
    }
    CP_COMMIT();
    // Qhi/Qlo/V tile 0 -> buffer 0 (group 1): each 64 rows x 8 segs = 512 slots
    #pragma unroll
    for (int i = 0; i < 2; i++) {
        int idx = tid + i * 256;               // 0..511
        int row = idx >> 3, seg = idx & 7;
        uint32_t doff = row * 144 + seg * 16;
        const size_t goff = (size_t)row * E + seg * 8;
        CP_ASYNC16(sb + AQHI_B + doff, qh_b + goff);
        CP_ASYNC16(sb + AQLO_B + doff, ql_b + goff);
        CP_ASYNC16(sb + AVH_B  + doff, v_b  + goff);
    }
    CP_COMMIT();
    CP_WAIT1();              // K resident
    __syncthreads();

    // Khi fp16 fragments in registers: m16 x k64 (4 k16-steps)
    uint32_t kfh[4][4];
    #pragma unroll
    for (int kk = 0; kk < 4; kk++) {
        float2 kv[4];
        const float* kfp = smf + AKF_B / 4;
        kv[0] = *(float2*)&kfp[(rb    ) * 68 + kk * 16 + 2 * cc];
        kv[1] = *(float2*)&kfp[(rb + 8) * 68 + kk * 16 + 2 * cc];
        kv[2] = *(float2*)&kfp[(rb    ) * 68 + kk * 16 + 2 * cc + 8];
        kv[3] = *(float2*)&kfp[(rb + 8) * 68 + kk * 16 + 2 * cc + 8];
        #pragma unroll
        for (int j = 0; j < 4; j++)
            kfh[kk][j] = f22h2(kv[j].x, kv[j].y);
    }
    __syncthreads();          // K region now reusable as P

    float mrow0 = -1e30f, mrow1 = -1e30f, lrow0 = 0.f, lrow1 = 0.f;
    float o[8][4] = {};

    for (int t0 = 0; t0 < Ss; t0 += 64) {
        int buf = (t0 >> 6) & 1;
        uint32_t bufo = buf * 9216;
        if (t0 + 64 < Ss) {
            uint32_t nbo = (buf ^ 1) * 9216;
            size_t src0 = (size_t)(t0 + 64) * E;
            #pragma unroll
            for (int i = 0; i < 2; i++) {
                int idx = tid + i * 256;
                int row = idx >> 3, seg = idx & 7;
                uint32_t doff = nbo + row * 144 + seg * 16;
                const size_t goff = src0 + (size_t)row * E + seg * 8;
                CP_ASYNC16(sb + AQHI_B + doff, qh_b + goff);
                CP_ASYNC16(sb + AQLO_B + doff, ql_b + goff);
                CP_ASYNC16(sb + AVH_B  + doff, v_b  + goff);
            }
            CP_COMMIT();
        }

        // S = Khi x (Qhi + Qlo)^T : 2 MMAs per k16-step
        float s[8][4] = {};
        #pragma unroll
        for (int kk = 0; kk < 4; kk++) {
            uint32_t koff = bufo + kk * 32;
            #pragma unroll
            for (int nt2 = 0; nt2 < 4; nt2++) {
                uint32_t qh[4], ql[4];
                LDMX4(qh[0], qh[1], qh[2], qh[3], sb + qhio[nt2] + koff);
                LDMX4(ql[0], ql[1], ql[2], ql[3], sb + qloo[nt2] + koff);
                mma_f16(s[2 * nt2    ], kfh[kk], qh[0], qh[2]);
                mma_f16(s[2 * nt2    ], kfh[kk], ql[0], ql[2]);
                mma_f16(s[2 * nt2 + 1], kfh[kk], qh[1], qh[3]);
                mma_f16(s[2 * nt2 + 1], kfh[kk], ql[1], ql[3]);
            }
        }

        // online softmax over t (rows in-warp: quad shfl reduce)
        float mx0 = -1e30f, mx1 = -1e30f;
        #pragma unroll
        for (int nt = 0; nt < 8; nt++) {
            mx0 = fmaxf(mx0, fmaxf(s[nt][0], s[nt][1]));
            mx1 = fmaxf(mx1, fmaxf(s[nt][2], s[nt][3]));
        }
        mx0 = fmaxf(mx0, __shfl_xor_sync(0xffffffffu, mx0, 1));
        mx0 = fmaxf(mx0, __shfl_xor_sync(0xffffffffu, mx0, 2));
        mx1 = fmaxf(mx1, __shfl_xor_sync(0xffffffffu, mx1, 1));
        mx1 = fmaxf(mx1, __shfl_xor_sync(0xffffffffu, mx1, 2));
        float mn0 = fmaxf(mrow0, mx0), mn1 = fmaxf(mrow1, mx1);
        float a0 = __expf(mrow0 - mn0), a1 = __expf(mrow1 - mn1);
        mrow0 = mn0; mrow1 = mn1;

        float ps0 = 0.f, ps1 = 0.f;
        #pragma unroll
        for (int nt = 0; nt < 8; nt++) {
            float p0 = __expf(s[nt][0] - mn0);
            float p1 = __expf(s[nt][1] - mn0);
            float p2 = __expf(s[nt][2] - mn1);
            float p3 = __expf(s[nt][3] - mn1);
            ps0 += p0 + p1;
            ps1 += p2 + p3;
            smu[AKF_B / 4 + (rb    ) * 36 + nt * 4 + cc] = f22h2(p0, p1);
            smu[AKF_B / 4 + (rb + 8) * 36 + nt * 4 + cc] = f22h2(p2, p3);
        }
        ps0 += __shfl_xor_sync(0xffffffffu, ps0, 1);
        ps0 += __shfl_xor_sync(0xffffffffu, ps0, 2);
        ps1 += __shfl_xor_sync(0xffffffffu, ps1, 1);
        ps1 += __shfl_xor_sync(0xffffffffu, ps1, 2);
        lrow0 = lrow0 * a0 + ps0;
        lrow1 = lrow1 * a1 + ps1;
        #pragma unroll
        for (int nt = 0; nt < 8; nt++) {
            o[nt][0] *= a0; o[nt][1] *= a0;
            o[nt][2] *= a1; o[nt][3] *= a1;
        }
        __syncwarp();   // this warp's P rows visible (warp-private rows)

        // O += P x V : P A-frags via ldmatrix, V B-frags via ldmatrix.trans
        #pragma unroll
        for (int kk = 0; kk < 4; kk++) {
            uint32_t pa[4];
            LDMX4(pa[0], pa[1], pa[2], pa[3], sb + poff + kk * 32);
            uint32_t vko = bufo + kk * 2304;       // 16 t-rows * 144B
            #pragma unroll
            for (int nt2 = 0; nt2 < 4; nt2++) {
                uint32_t vf[4];
                LDMX4T(vf[0], vf[1], vf[2], vf[3], sb + vofft[nt2] + vko);
                mma_f16(o[2 * nt2    ], pa, vf[0], vf[1]);
                mma_f16(o[2 * nt2 + 1], pa, vf[2], vf[3]);
            }
        }
        CP_WAIT0();
        __syncthreads();    // next tiles resident; all warps done with buf
    }

    float i0 = 1.f / lrow0, i1 = 1.f / lrow1;
    uint32_t* orow0 = (uint32_t*)(o_out + (size_t)(b * Ss + s0 + rb) * E + hh * 64);
    uint32_t* orow1 = (uint32_t*)(o_out + (size_t)(b * Ss + s0 + rb + 8) * E + hh * 64);
    #pragma unroll
    for (int nt = 0; nt < 8; nt++) {
        orow0[nt * 4 + cc] = f22h2(o[nt][0] * i0, o[nt][1] * i0);
        orow1[nt * 4 + cc] = f22h2(o[nt][2] * i1, o[nt][3] * i1);
    }
}

// ---------------- host launch ----------------
extern "C" void kernel_launch(void* const* d_in, const int* in_sizes, int n_in,
                              void* d_out, int out_size) {
    const float* x     = (const float*)d_in[0];
    const float* Wq    = (const float*)d_in[1];
    const float* bq    = (const float*)d_in[2];
    const float* Wk    = (const float*)d_in[3];
    const float* bk    = (const float*)d_in[4];
    const float* Wv    = (const float*)d_in[5];
    const float* bv    = (const float*)d_in[6];
    const float* Wo    = (const float*)d_in[7];
    const float* bo    = (const float*)d_in[8];
    const float* ln1_g = (const float*)d_in[9];
    const float* ln1_b = (const float*)d_in[10];
    const float* ln2_g = (const float*)d_in[11];
    const float* ln2_b = (const float*)d_in[12];
    const float* W1    = (const float*)d_in[13];
    const float* b1    = (const float*)d_in[14];
    const float* W2    = (const float*)d_in[15];
    const float* b2    = (const float*)d_in[16];
    float* out = (float*)d_out;

    __half *p_h, *p_qhi, *p_qlo, *p_v, *p_Wqkv, *p_WoT, *p_W1T, *p_W2T, *p_o, *p_h2, *p_m1;
    float *p_k, *p_bqkv, *p_x1;
    cudaGetSymbolAddress((void**)&p_h,    g_h);
    cudaGetSymbolAddress((void**)&p_qhi,  g_qhi);
    cudaGetSymbolAddress((void**)&p_qlo,  g_qlo);
    cudaGetSymbolAddress((void**)&p_k,    g_k);
    cudaGetSymbolAddress((void**)&p_v,    g_v);
    cudaGetSymbolAddress((void**)&p_Wqkv, g_Wqkv);
    cudaGetSymbolAddress((void**)&p_bqkv, g_bqkv);
    cudaGetSymbolAddress((void**)&p_WoT,  g_WoT);
    cudaGetSymbolAddress((void**)&p_W1T,  g_W1T);
    cudaGetSymbolAddress((void**)&p_W2T,  g_W2T);
    cudaGetSymbolAddress((void**)&p_o,    g_o);
    cudaGetSymbolAddress((void**)&p_x1,   g_x1);
    cudaGetSymbolAddress((void**)&p_h2,   g_h2);
    cudaGetSymbolAddress((void**)&p_m1,   g_m1);

    cudaFuncSetAttribute(gemm_h<false, false>, cudaFuncAttributeMaxDynamicSharedMemorySize, GEMMH_SMEM);
    cudaFuncSetAttribute(gemm_h<true,  true>,  cudaFuncAttributeMaxDynamicSharedMemorySize, GEMMH_SMEM);
    cudaFuncSetAttribute(gemm_qkv,             cudaFuncAttributeMaxDynamicSharedMemorySize, GEMMH_SMEM);
    cudaFuncSetAttribute(attn_mma_kernel,      cudaFuncAttributeMaxDynamicSharedMemorySize, ATT_SMEM);

    // 1. pack fused QKV weight (transposed, fp16) + bias; transpose Wo, W1, W2 (fp16)
    pack_qkv_kernel<<<(3 * E * E + 255) / 256, 256>>>(Wq, Wk, Wv, bq, bk, bv);
    transpose_kernel<<<dim3(E / 32, E / 32),  dim3(32, 8)>>>(Wo, p_WoT, E, E);
    transpose_kernel<<<dim3(E / 32, Ff / 32), dim3(32, 8)>>>(W1, p_W1T, E, Ff);
    transpose_kernel<<<dim3(Ff / 32, E / 32), dim3(32, 8)>>>(W2, p_W2T, Ff, E);

    // 2. LN1 (fp16 out)
    ln_kernel<<<NT, 256>>>(x, ln1_g, ln1_b, p_h);

    // 3. fused QKV projection: epilogue pre-splits Q (hi/lo fp16), K fp32, V fp16
    gemm_qkv<<<dim3(3 * E / 128, NT / 128), 256, GEMMH_SMEM>>>(p_h, p_Wqkv, p_bqkv, p_qhi, p_qlo, p_k, p_v);

    // 4. attention (2-term split-fp16 S, fp16 PV) -> fp16 o
    attn_mma_kernel<<<dim3(Ss / 128, H * Bb), 256, ATT_SMEM>>>(p_qhi, p_qlo, p_k, p_v, p_o);

    // 5. output projection + residual (fp32 out)
    gemm_h<false, false><<<dim3(E / 128, NT / 128), 256, GEMMH_SMEM>>>(p_o, p_WoT, bo, x, p_x1, NT, E, E);

    // 6. LN2 (fp16 out)
    ln_kernel<<<NT, 256>>>(p_x1, ln2_g, ln2_b, p_h2);

    // 7. MLP up + ReLU (fp16 out -> feeds MLP down as A)
    gemm_h<true, true><<<dim3(Ff / 128, NT / 128), 256, GEMMH_SMEM>>>(p_h2, p_W1T, b1, nullptr, p_m1, NT, Ff, E);

    // 8. MLP down + residual -> fp32 output
    gemm_h<false, false><<<dim3(E / 128, NT / 128), 256, GEMMH_SMEM>>>(p_m1, p_W2T, b2, p_x1, out, NT, E, Ff);
}

// round 16
// speedup vs baseline: 1.1908x; 1.0031x over previous
#include <cuda_runtime.h>
#include <cuda_fp16.h>
#include <cstdint>
#include <math.h>

#define E    1024
#define Dh   64
#define H    16
#define Ff   4096
#define Bb   2
#define Ss   2048
#define NT   (Bb*Ss)     // 4096 tokens
#define EPS  1e-5f

// ---------------- scratch (static device memory; no allocation) ----------------
__device__ __half g_h   [NT * E];        // LN1 output (fp16)
__device__ __half g_qhi [NT * E];        // Q hi fp16
__device__ __half g_qlo [NT * E];        // Q lo fp16 (residual)
__device__ float  g_k   [NT * E];        // K fp32
__device__ __half g_v   [NT * E];        // V fp16
__device__ __half g_Wqkv[3 * E * E];     // packed W_qkv^T : [3072, 1024] (N,K) fp16
__device__ float  g_bqkv[3 * E];
__device__ __half g_WoT [E * E];         // Wo^T  fp16
__device__ __half g_W1T [Ff * E];        // W1^T  fp16
__device__ __half g_W2T [E * Ff];        // W2^T  fp16
__device__ __half g_o   [NT * E];        // attention out (fp16)
__device__ float  g_x1  [NT * E];        // after first residual (fp32)
__device__ __half g_h2  [NT * E];        // LN2 output (fp16)
__device__ __half g_m1  [NT * Ff];       // relu(h2 @ W1 + b1) (fp16)

// ======================= helpers =======================
__device__ __forceinline__ uint32_t smem_u32(const void* p) {
    uint32_t a;
    asm("{ .reg .u64 t; cvta.to.shared.u64 t, %1; cvt.u32.u64 %0, t; }" : "=r"(a) : "l"(p));
    return a;
}
__device__ __forceinline__ uint32_t f22h2(float a, float b) {
    __half2 h = __floats2half2_rn(a, b);
    return *(uint32_t*)&h;
}
#define CP_ASYNC16(dst, src) \
    asm volatile("cp.async.cg.shared.global [%0], [%1], 16;" :: "r"((uint32_t)(dst)), "l"(src))
#define CP_COMMIT() asm volatile("cp.async.commit_group;" ::: "memory")
#define CP_WAIT0()  asm volatile("cp.async.wait_group 0;" ::: "memory")
#define CP_WAIT1()  asm volatile("cp.async.wait_group 1;" ::: "memory")

#define LDMX4(r0, r1, r2, r3, addr) \
    asm volatile("ldmatrix.sync.aligned.m8n8.x4.shared.b16 {%0,%1,%2,%3}, [%4];" \
        : "=r"(r0), "=r"(r1), "=r"(r2), "=r"(r3) : "r"(addr))
#define LDMX4T(r0, r1, r2, r3, addr) \
    asm volatile("ldmatrix.sync.aligned.m8n8.x4.trans.shared.b16 {%0,%1,%2,%3}, [%4];" \
        : "=r"(r0), "=r"(r1), "=r"(r2), "=r"(r3) : "r"(addr))

// m16n8k16 fp16 mma: D(f32) += A(f16) * B(f16)
__device__ __forceinline__ void mma_f16(float* c, const uint32_t* a, uint32_t b0, uint32_t b1) {
    asm volatile(
        "mma.sync.aligned.m16n8k16.row.col.f32.f16.f16.f32 "
        "{%0,%1,%2,%3}, {%4,%5,%6,%7}, {%8,%9}, {%0,%1,%2,%3};"
        : "+f"(c[0]), "+f"(c[1]), "+f"(c[2]), "+f"(c[3])
        : "r"(a[0]), "r"(a[1]), "r"(a[2]), "r"(a[3]), "r"(b0), "r"(b1));
}

// ---------------- prolog: coalesced QKV weight pack ----------------
// g_Wqkv[(wh*1024 + h*64 + d) * 1024 + e] = fp16(W_wh[(h*E + e)*64 + d])
// grid (E/64, 2, 48): x -> e0, y -> d0 (0/32), z -> wh*16+h. block (32,8).
__global__ void pack_qkv2_kernel(const float* __restrict__ Wq, const float* __restrict__ Wk,
                                 const float* __restrict__ Wv) {
    __shared__ float t[32][67];
    int e0 = blockIdx.x * 64;
    int d0 = blockIdx.y * 32;
    int z  = blockIdx.z;
    int wh = z >> 4, h = z & 15;
    const float* W = (wh == 0) ? Wq : (wh == 1) ? Wk : Wv;
    W += (size_t)h * E * Dh;

    int x = threadIdx.x, y = threadIdx.y;
    // read 64 e-rows x 32 d-cols (coalesced: consecutive x -> consecutive d)
    #pragma unroll
    for (int i = 0; i < 8; i++) {
        int ee = y + i * 8;
        t[x][ee] = W[(size_t)(e0 + ee) * Dh + d0 + x];
        int ee2 = ee + 32;
        t[x][ee2 - 32] = t[x][ee2 - 32];  // placeholder (avoided below)
    }
    // second half of e-rows
    #pragma unroll
    for (int i = 0; i < 8; i++) {
        int ee = y + i * 8;               // reuse: actually need 64 rows; do in 2 waves
        (void)ee;
    }
    // NOTE: rewritten simple version below (two 32-row waves with sync)
    __syncthreads();
    // The above filled rows e0..e0+? — to keep it simple and correct, redo cleanly:
    // wave covers only 32 e at a time; handle both halves explicitly.
    // (t currently holds e-half 0 from the first loop; write it, then do half 1.)
    #pragma unroll
    for (int half = 0; half < 2; half++) {
        if (half == 1) {
            __syncthreads();
            #pragma unroll
            for (int i = 0; i < 4; i++) {
                int ee = y + i * 8;       // 0..31
                t[x][ee] = W[(size_t)(e0 + 32 + ee) * Dh + d0 + x];
            }
            __syncthreads();
        } else {
            // ensure first half really loaded rows 0..31 only
            __syncthreads();
        }
        int ebase = e0 + half * 32;
        #pragma unroll
        for (int i = 0; i < 4; i++) {
            int dd = y + i * 8;           // 0..31
            int e2 = x;                   // 0..31 -> one half2 each (2 e not needed; 32 e per wave)
            // write 32 e as 16 half2 per row would need 16 threads; instead each
            // thread writes one half (32 x 2B = 64B). Use half2 across pairs:
            if ((e2 & 1) == 0) {
                __half2 hv = __floats2half2_rn(t[dd][e2], t[dd][e2 + 1]);
                *(__half2*)&g_Wqkv[(size_t)(wh * 1024 + h * 64 + d0 + dd) * 1024 + ebase + e2] = hv;
            }
        }
    }
}

__global__ void pack_bias_kernel(const float* __restrict__ bq, const float* __restrict__ bk,
                                 const float* __restrict__ bv) {
    int i = blockIdx.x * blockDim.x + threadIdx.x;
    if (i < 3 * E) {
        const float* bs = (i < E) ? bq : (i < 2 * E) ? bk : bv;
        g_bqkv[i] = bs[i % E];
    }
}

// out[n*K + k] = fp16(in[k*N + n]) ; vectorized: 64-wide k tiles, half2 writes
__global__ void transpose_kernel(const float* __restrict__ in, __half* __restrict__ out,
                                 int K, int N) {
    __shared__ float t[32][67];
    int k0 = blockIdx.x * 64, n0 = blockIdx.y * 32;
    int x = threadIdx.x, y = threadIdx.y;     // 32 x 8
    // read 64 k-rows x 32 n-cols (coalesced over x = n)
    #pragma unroll
    for (int half = 0; half < 2; half++) {
        __syncthreads();
        #pragma unroll
        for (int i = 0; i < 4; i++) {
            int kk = y + i * 8;               // 0..31
            t[x][kk] = in[(size_t)(k0 + half * 32 + kk) * N + n0 + x];
        }
        __syncthreads();
        // write 32 n-rows x 32 k-cols as half2 (16 half2 per row)
        #pragma unroll
        for (int i = 0; i < 4; i++) {
            int nn = y + i * 8;               // 0..31
            if ((x & 1) == 0) {
                __half2 hv = __floats2half2_rn(t[nn][x], t[nn][x + 1]);
                *(__half2*)&out[(size_t)(n0 + nn) * K + k0 + half * 32 + x] = hv;
            }
        }
    }
}

// ---------------- layernorm (fp16 output) ----------------
__global__ void ln_kernel(const float* __restrict__ x, const float* __restrict__ g,
                          const float* __restrict__ b, __half* __restrict__ out) {
    int row = blockIdx.x;
    int tid = threadIdx.x;
    const float4 v = ((const float4*)(x + (size_t)row * E))[tid];
    float s  = v.x + v.y + v.z + v.w;
    float ss = v.x * v.x + v.y * v.y + v.z * v.z + v.w * v.w;
    #pragma unroll
    for (int o = 16; o; o >>= 1) {
        s  += __shfl_xor_sync(0xffffffffu, s,  o);
        ss += __shfl_xor_sync(0xffffffffu, ss, o);
    }
    __shared__ float sm[8], sm2[8];
    if ((tid & 31) == 0) { sm[tid >> 5] = s; sm2[tid >> 5] = ss; }
    __syncthreads();
    float tot = 0.f, tot2 = 0.f;
    #pragma unroll
    for (int i = 0; i < 8; i++) { tot += sm[i]; tot2 += sm2[i]; }
    float mean = tot * (1.0f / E);
    float var  = tot2 * (1.0f / E) - mean * mean;
    float inv  = rsqrtf(var + EPS);
    const float4 gg = ((const float4*)g)[tid];
    const float4 bb = ((const float4*)b)[tid];
    __half2* orow = (__half2*)(out + (size_t)row * E);
    orow[2 * tid]     = __floats2half2_rn((v.x - mean) * inv * gg.x + bb.x,
                                          (v.y - mean) * inv * gg.y + bb.y);
    orow[2 * tid + 1] = __floats2half2_rn((v.z - mean) * inv * gg.z + bb.z,
                                          (v.w - mean) * inv * gg.w + bb.w);
}

// ---------------- fp16 warp-MMA GEMM core macros ----------------
#define LDH 72
#define TILE_H (128 * LDH * 2)          // 18432 bytes per tile
#define STAGE_H (2 * TILE_H)            // 36864
#define GEMMH_SMEM (3 * STAGE_H)        // 110592 -> 2 CTAs/SM

// generic GEMM: C = A[M,K] @ Bt[N,K]^T (+bias)(+relu)(+res)
template<bool RELU, bool OUT_HALF>
__global__ __launch_bounds__(256, 2)
void gemm_h(const __half* __restrict__ A, const __half* __restrict__ Bt,
            const float* __restrict__ bias, const float* __restrict__ res,
            void* __restrict__ Cv, int M, int N, int K) {
    extern __shared__ char smem[];
    uint32_t sb = smem_u32(smem);
    int tid = threadIdx.x;
    int lane = tid & 31, wid = tid >> 5;
    int warp_m = wid & 3, warp_n = wid >> 2;
    int n0 = blockIdx.x * 128, m0 = blockIdx.y * 128;

    const __half* Abase = A  + (size_t)m0 * K;
    const __half* Bbase = Bt + (size_t)n0 * K;
    int NC = K >> 6;

    int lt = lane >> 3, lr = lane & 7;
    uint32_t aoff[2], boff[4];
    #pragma unroll
    for (int mt = 0; mt < 2; mt++)
        aoff[mt] = ((warp_m * 32 + mt * 16 + (lt & 1) * 8 + lr) * 36 + (lt >> 1) * 4) * 4;
    #pragma unroll
    for (int nt2 = 0; nt2 < 4; nt2++)
        boff[nt2] = TILE_H + ((warp_n * 64 + nt2 * 16 + (lt & 1) * 8 + lr) * 36 + (lt >> 1) * 4) * 4;

    #pragma unroll
    for (int st = 0; st < 2; st++) {
        uint32_t bufo = st * STAGE_H;
        int koff = st * 64;
        #pragma unroll
        for (int i = 0; i < 4; i++) {
            int idx = tid + i * 256;
            int row = idx >> 3, seg = idx & 7;
            CP_ASYNC16(sb + bufo + row * 144 + seg * 16,
                       Abase + (size_t)row * K + koff + seg * 8);
        }
        #pragma unroll
        for (int i = 0; i < 4; i++) {
            int idx = tid + i * 256;
            int row = idx >> 3, seg = idx & 7;
            CP_ASYNC16(sb + bufo + TILE_H + row * 144 + seg * 16,
                       Bbase + (size_t)row * K + koff + seg * 8);
        }
        CP_COMMIT();
    }
    CP_WAIT1();
    __syncthreads();

    float acc[2][8][4] = {};
    int cb = 0, pb = 2;
    int r = lane >> 2, cc = lane & 3;

    for (int c = 0; c < NC; c++) {
        if (c + 2 < NC) {
            uint32_t bufo = pb * STAGE_H;
            const __half* as = Abase + (c + 2) * 64;
            const __half* bs = Bbase + (c + 2) * 64;
            #pragma unroll
            for (int i = 0; i < 4; i++) {
                int idx = tid + i * 256;
                int row = idx >> 3, seg = idx & 7;
                CP_ASYNC16(sb + bufo + row * 144 + seg * 16,
                           as + (size_t)row * K + seg * 8);
            }
            #pragma unroll
            for (int i = 0; i < 4; i++) {
                int idx = tid + i * 256;
                int row = idx >> 3, seg = idx & 7;
                CP_ASYNC16(sb + bufo + TILE_H + row * 144 + seg * 16,
                           bs + (size_t)row * K + seg * 8);
            }
        }
        CP_COMMIT();

        uint32_t stage = sb + cb * STAGE_H;
        #pragma unroll
        for (int kk = 0; kk < 4; kk++) {
            uint32_t koff = kk * 32;
            uint32_t afr[2][4];
            LDMX4(afr[0][0], afr[0][1], afr[0][2], afr[0][3], stage + aoff[0] + koff);
            LDMX4(afr[1][0], afr[1][1], afr[1][2], afr[1][3], stage + aoff[1] + koff);
            #pragma unroll
            for (int nt2 = 0; nt2 < 4; nt2++) {
                uint32_t bfr[4];
                LDMX4(bfr[0], bfr[1], bfr[2], bfr[3], stage + boff[nt2] + koff);
                mma_f16(acc[0][2 * nt2    ], afr[0], bfr[0], bfr[2]);
                mma_f16(acc[1][2 * nt2    ], afr[1], bfr[0], bfr[2]);
                mma_f16(acc[0][2 * nt2 + 1], afr[0], bfr[1], bfr[3]);
                mma_f16(acc[1][2 * nt2 + 1], afr[1], bfr[1], bfr[3]);
            }
        }
        CP_WAIT1();
        __syncthreads();
        cb = (cb + 1 == 3) ? 0 : cb + 1;
        pb = (pb + 1 == 3) ? 0 : pb + 1;
    }

    #pragma unroll
    for (int mt = 0; mt < 2; mt++) {
        #pragma unroll
        for (int nt = 0; nt < 8; nt++) {
            int col = n0 + warp_n * 64 + nt * 8 + cc * 2;
            float2 bv = *(const float2*)&bias[col];
            #pragma unroll
            for (int rr = 0; rr < 2; rr++) {
                int row = m0 + warp_m * 32 + mt * 16 + r + rr * 8;
                float vx = acc[mt][nt][rr * 2 + 0] + bv.x;
                float vy = acc[mt][nt][rr * 2 + 1] + bv.y;
                if (RELU) { vx = fmaxf(vx, 0.f); vy = fmaxf(vy, 0.f); }
                if (res) {
                    float2 rv = *(const float2*)&res[(size_t)row * N + col];
                    vx += rv.x; vy += rv.y;
                }
                if (OUT_HALF) {
                    *(uint32_t*)&((__half*)Cv)[(size_t)row * N + col] = f22h2(vx, vy);
                } else {
                    float2 v = { vx, vy };
                    *(float2*)&((float*)Cv)[(size_t)row * N + col] = v;
                }
            }
        }
    }
}

// QKV GEMM: same mainloop, epilogue splits by region: Q -> qhi/qlo fp16, K -> fp32, V -> fp16
__global__ __launch_bounds__(256, 2)
void gemm_qkv(const __half* __restrict__ A, const __half* __restrict__ Bt,
              const float* __restrict__ bias,
              __half* __restrict__ qhi, __half* __restrict__ qlo,
              float* __restrict__ kf, __half* __restrict__ vf) {
    const int N = 3 * E, K = E;
    (void)N;
    extern __shared__ char smem[];
    uint32_t sb = smem_u32(smem);
    int tid = threadIdx.x;
    int lane = tid & 31, wid = tid >> 5;
    int warp_m = wid & 3, warp_n = wid >> 2;
    int n0 = blockIdx.x * 128, m0 = blockIdx.y * 128;

    const __half* Abase = A  + (size_t)m0 * K;
    const __half* Bbase = Bt + (size_t)n0 * K;
    int NC = K >> 6;

    int lt = lane >> 3, lr = lane & 7;
    uint32_t aoff[2], boff[4];
    #pragma unroll
    for (int mt = 0; mt < 2; mt++)
        aoff[mt] = ((warp_m * 32 + mt * 16 + (lt & 1) * 8 + lr) * 36 + (lt >> 1) * 4) * 4;
    #pragma unroll
    for (int nt2 = 0; nt2 < 4; nt2++)
        boff[nt2] = TILE_H + ((warp_n * 64 + nt2 * 16 + (lt & 1) * 8 + lr) * 36 + (lt >> 1) * 4) * 4;

    #pragma unroll
    for (int st = 0; st < 2; st++) {
        uint32_t bufo = st * STAGE_H;
        int koff = st * 64;
        #pragma unroll
        for (int i = 0; i < 4; i++) {
            int idx = tid + i * 256;
            int row = idx >> 3, seg = idx & 7;
            CP_ASYNC16(sb + bufo + row * 144 + seg * 16,
                       Abase + (size_t)row * K + koff + seg * 8);
        }
        #pragma unroll
        for (int i = 0; i < 4; i++) {
            int idx = tid + i * 256;
            int row = idx >> 3, seg = idx & 7;
            CP_ASYNC16(sb + bufo + TILE_H + row * 144 + seg * 16,
                       Bbase + (size_t)row * K + koff + seg * 8);
        }
        CP_COMMIT();
    }
    CP_WAIT1();
    __syncthreads();

    float acc[2][8][4] = {};
    int cb = 0, pb = 2;
    int r = lane >> 2, cc = lane & 3;

    for (int c = 0; c < NC; c++) {
        if (c + 2 < NC) {
            uint32_t bufo = pb * STAGE_H;
            const __half* as = Abase + (c + 2) * 64;
            const __half* bs = Bbase + (c + 2) * 64;
            #pragma unroll
            for (int i = 0; i < 4; i++) {
                int idx = tid + i * 256;
                int row = idx >> 3, seg = idx & 7;
                CP_ASYNC16(sb + bufo + row * 144 + seg * 16,
                           as + (size_t)row * K + seg * 8);
            }
            #pragma unroll
            for (int i = 0; i < 4; i++) {
                int idx = tid + i * 256;
                int row = idx >> 3, seg = idx & 7;
                CP_ASYNC16(sb + bufo + TILE_H + row * 144 + seg * 16,
                           bs + (size_t)row * K + seg * 8);
            }
        }
        CP_COMMIT();

        uint32_t stage = sb + cb * STAGE_H;
        #pragma unroll
        for (int kk = 0; kk < 4; kk++) {
            uint32_t koff = kk * 32;
            uint32_t afr[2][4];
            LDMX4(afr[0][0], afr[0][1], afr[0][2], afr[0][3], stage + aoff[0] + koff);
            LDMX4(afr[1][0], afr[1][1], afr[1][2], afr[1][3], stage + aoff[1] + koff);
            #pragma unroll
            for (int nt2 = 0; nt2 < 4; nt2++) {
                uint32_t bfr[4];
                LDMX4(bfr[0], bfr[1], bfr[2], bfr[3], stage + boff[nt2] + koff);
                mma_f16(acc[0][2 * nt2    ], afr[0], bfr[0], bfr[2]);
                mma_f16(acc[1][2 * nt2    ], afr[1], bfr[0], bfr[2]);
                mma_f16(acc[0][2 * nt2 + 1], afr[0], bfr[1], bfr[3]);
                mma_f16(acc[1][2 * nt2 + 1], afr[1], bfr[1], bfr[3]);
            }
        }
        CP_WAIT1();
        __syncthreads();
        cb = (cb + 1 == 3) ? 0 : cb + 1;
        pb = (pb + 1 == 3) ? 0 : pb + 1;
    }

    // epilogue: region 0 = Q (hi/lo fp16), 1 = K (fp32), 2 = V (fp16)
    int region = n0 >> 10;
    #pragma unroll
    for (int mt = 0; mt < 2; mt++) {
        #pragma unroll
        for (int nt = 0; nt < 8; nt++) {
            int col = n0 + warp_n * 64 + nt * 8 + cc * 2;
            float2 bv = *(const float2*)&bias[col];
            int cr = col - region * E;
            #pragma unroll
            for (int rr = 0; rr < 2; rr++) {
                int row = m0 + warp_m * 32 + mt * 16 + r + rr * 8;
                float vx = acc[mt][nt][rr * 2 + 0] + bv.x;
                float vy = acc[mt][nt][rr * 2 + 1] + bv.y;
                size_t off = (size_t)row * E + cr;
                if (region == 1) {
                    float2 v = { vx, vy };
                    *(float2*)&kf[off] = v;
                } else if (region == 2) {
                    *(uint32_t*)&vf[off] = f22h2(vx, vy);
                } else {
                    __half hx = __float2half_rn(vx), hy = __float2half_rn(vy);
                    __half2 hh2; hh2.x = hx; hh2.y = hy;
                    *(__half2*)&qhi[off] = hh2;
                    *(uint32_t*)&qlo[off] = f22h2(vx - __half2float(hx),
                                                  vy - __half2float(hy));
                }
            }
        }
    }
}

// ---------------- fp16 MMA flash attention (rows = keys, softmax over queries) --
// CTA: 128 key rows, 8 warps. Q pre-split (qhi/qlo fp16), V fp16, K fp32->Khi regs.
// 2-term S: S = Khi*(Qhi+Qlo).
#define AQHI_B 0
#define AQLO_B 18432
#define AVH_B  36864
#define AKF_B  55296
#define ATT_SMEM (AKF_B + 128 * 68 * 4)   // 90112 bytes -> 2 CTAs/SM

__global__ __launch_bounds__(256)
void attn_mma_kernel(const __half* __restrict__ qhi_g, const __half* __restrict__ qlo_g,
                     const float* __restrict__ k_g, const __half* __restrict__ v_g,
                     __half* __restrict__ o_out) {
    extern __shared__ float smf[];
    uint32_t sb = smem_u32(smf);
    uint32_t* smu = (uint32_t*)smf;

    int hb = blockIdx.y;
    int hh = hb >> 1, b = hb & 1;
    int s0 = blockIdx.x * 128;
    int tid = threadIdx.x, lane = tid & 31, wid = tid >> 5;
    int r = lane >> 2, cc = lane & 3;
    int rb = wid * 16 + r;

    // ldmatrix per-thread byte offsets
    int lt = lane >> 3, lr = lane & 7;
    uint32_t qhio[4], qloo[4], vofft[4], poff;
    {
        uint32_t rowsel = (lt & 1) * 8 + lr;
        uint32_t wordsel = (lt >> 1) * 4;
        #pragma unroll
        for (int nt2 = 0; nt2 < 4; nt2++) {
            uint32_t ro = ((nt2 * 16 + rowsel) * 36 + wordsel) * 4;   // B frags (n-rows)
            qhio[nt2] = AQHI_B + ro;
            qloo[nt2] = AQLO_B + ro;
            // V trans: rows = t (k dim), col bytes = d offset
            vofft[nt2] = AVH_B + rowsel * 144 + nt2 * 32 + (lt >> 1) * 16;
        }
        poff = AKF_B + ((wid * 16 + rowsel) * 36 + wordsel) * 4;
    }

    size_t tok0 = (size_t)(b * Ss);
    const float*  kbase = k_g   + (tok0 + s0) * E + hh * 64;
    const __half* qh_b  = qhi_g + tok0 * E + hh * 64;
    const __half* ql_b  = qlo_g + tok0 * E + hh * 64;
    const __half* v_b   = v_g   + tok0 * E + hh * 64;

    // K tile [128 x 64] fp32 (group 0)
    #pragma unroll
    for (int i = 0; i < 8; i++) {
        int idx = tid + i * 256;               // 0..2047
        int row = idx >> 4, seg = idx & 15;
        CP_ASYNC16(sb + AKF_B + row * 272 + seg * 16,
                   kbase + (size_t)row * E + seg * 4);
    }
    CP_COMMIT();
    // Qhi/Qlo/V tile 0 -> buffer 0 (group 1): each 64 rows x 8 segs = 512 slots
    #pragma unroll
    for (int i = 0; i < 2; i++) {
        int idx = tid + i * 256;               // 0..511
        int row = idx >> 3, seg = idx & 7;
        uint32_t doff = row * 144 + seg * 16;
        const size_t goff = (size_t)row * E + seg * 8;
        CP_ASYNC16(sb + AQHI_B + doff, qh_b + goff);
        CP_ASYNC16(sb + AQLO_B + doff, ql_b + goff);
        CP_ASYNC16(sb + AVH_B  + doff, v_b  + goff);
    }
    CP_COMMIT();
    CP_WAIT1();              // K resident
    __syncthreads();

    // Khi fp16 fragments in registers: m16 x k64 (4 k16-steps)
    uint32_t kfh[4][4];
    #pragma unroll
    for (int kk = 0; kk < 4; kk++) {
        float2 kv[4];
        const float* kfp = smf + AKF_B / 4;
        kv[0] = *(float2*)&kfp[(rb    ) * 68 + kk * 16 + 2 * cc];
        kv[1] = *(float2*)&kfp[(rb + 8) * 68 + kk * 16 + 2 * cc];
        kv[2] = *(float2*)&kfp[(rb    ) * 68 + kk * 16 + 2 * cc + 8];
        kv[3] = *(float2*)&kfp[(rb + 8) * 68 + kk * 16 + 2 * cc + 8];
        #pragma unroll
        for (int j = 0; j < 4; j++)
            kfh[kk][j] = f22h2(kv[j].x, kv[j].y);
    }
    __syncthreads();          // K region now reusable as P

    float mrow0 = -1e30f, mrow1 = -1e30f, lrow0 = 0.f, lrow1 = 0.f;
    float o[8][4] = {};

    for (int t0 = 0; t0 < Ss; t0 += 64) {
        int buf = (t0 >> 6) & 1;
        uint32_t bufo = buf * 9216;
        if (t0 + 64 < Ss) {
            uint32_t nbo = (buf ^ 1) * 9216;
            size_t src0 = (size_t)(t0 + 64) * E;
            #pragma unroll
            for (int i = 0; i < 2; i++) {
                int idx = tid + i * 256;
                int row = idx >> 3, seg = idx & 7;
                uint32_t doff = nbo + row * 144 + seg * 16;
                const size_t goff = src0 + (size_t)row * E + seg * 8;
                CP_ASYNC16(sb + AQHI_B + doff, qh_b + goff);
                CP_ASYNC16(sb + AQLO_B + doff, ql_b + goff);
                CP_ASYNC16(sb + AVH_B  + doff, v_b  + goff);
            }
            CP_COMMIT();
        }

        // S = Khi x (Qhi + Qlo)^T : 2 MMAs per k16-step
        float s[8][4] = {};
        #pragma unroll
        for (int kk = 0; kk < 4; kk++) {
            uint32_t koff = bufo + kk * 32;
            #pragma unroll
            for (int nt2 = 0; nt2 < 4; nt2++) {
                uint32_t qh[4], ql[4];
                LDMX4(qh[0], qh[1], qh[2], qh[3], sb + qhio[nt2] + koff);
                LDMX4(ql[0], ql[1], ql[2], ql[3], sb + qloo[nt2] + koff);
                mma_f16(s[2 * nt2    ], kfh[kk], qh[0], qh[2]);
                mma_f16(s[2 * nt2    ], kfh[kk], ql[0], ql[2]);
                mma_f16(s[2 * nt2 + 1], kfh[kk], qh[1], qh[3]);
                mma_f16(s[2 * nt2 + 1], kfh[kk], ql[1], ql[3]);
            }
        }

        // online softmax over t (rows in-warp: quad shfl reduce)
        float mx0 = -1e30f, mx1 = -1e30f;
        #pragma unroll
        for (int nt = 0; nt < 8; nt++) {
            mx0 = fmaxf(mx0, fmaxf(s[nt][0], s[nt][1]));
            mx1 = fmaxf(mx1, fmaxf(s[nt][2], s[nt][3]));
        }
        mx0 = fmaxf(mx0, __shfl_xor_sync(0xffffffffu, mx0, 1));
        mx0 = fmaxf(mx0, __shfl_xor_sync(0xffffffffu, mx0, 2));
        mx1 = fmaxf(mx1, __shfl_xor_sync(0xffffffffu, mx1, 1));
        mx1 = fmaxf(mx1, __shfl_xor_sync(0xffffffffu, mx1, 2));
        float mn0 = fmaxf(mrow0, mx0), mn1 = fmaxf(mrow1, mx1);
        float a0 = __expf(mrow0 - mn0), a1 = __expf(mrow1 - mn1);
        mrow0 = mn0; mrow1 = mn1;

        float ps0 = 0.f, ps1 = 0.f;
        #pragma unroll
        for (int nt = 0; nt < 8; nt++) {
            float p0 = __expf(s[nt][0] - mn0);
            float p1 = __expf(s[nt][1] - mn0);
            float p2 = __expf(s[nt][2] - mn1);
            float p3 = __expf(s[nt][3] - mn1);
            ps0 += p0 + p1;
            ps1 += p2 + p3;
            smu[AKF_B / 4 + (rb    ) * 36 + nt * 4 + cc] = f22h2(p0, p1);
            smu[AKF_B / 4 + (rb + 8) * 36 + nt * 4 + cc] = f22h2(p2, p3);
        }
        ps0 += __shfl_xor_sync(0xffffffffu, ps0, 1);
        ps0 += __shfl_xor_sync(0xffffffffu, ps0, 2);
        ps1 += __shfl_xor_sync(0xffffffffu, ps1, 1);
        ps1 += __shfl_xor_sync(0xffffffffu, ps1, 2);
        lrow0 = lrow0 * a0 + ps0;
        lrow1 = lrow1 * a1 + ps1;
        #pragma unroll
        for (int nt = 0; nt < 8; nt++) {
            o[nt][0] *= a0; o[nt][1] *= a0;
            o[nt][2] *= a1; o[nt][3] *= a1;
        }
        __syncwarp();   // this warp's P rows visible (warp-private rows)

        // O += P x V : P A-frags via ldmatrix, V B-frags via ldmatrix.trans
        #pragma unroll
        for (int kk = 0; kk < 4; kk++) {
            uint32_t pa[4];
            LDMX4(pa[0], pa[1], pa[2], pa[3], sb + poff + kk * 32);
            uint32_t vko = bufo + kk * 2304;       // 16 t-rows * 144B
            #pragma unroll
            for (int nt2 = 0; nt2 < 4; nt2++) {
                uint32_t vf[4];
                LDMX4T(vf[0], vf[1], vf[2], vf[3], sb + vofft[nt2] + vko);
                mma_f16(o[2 * nt2    ], pa, vf[0], vf[1]);
                mma_f16(o[2 * nt2 + 1], pa, vf[2], vf[3]);
            }
        }
        CP_WAIT0();
        __syncthreads();    // next tiles resident; all warps done with buf
    }

    float i0 = 1.f / lrow0, i1 = 1.f / lrow1;
    uint32_t* orow0 = (uint32_t*)(o_out + (size_t)(b * Ss + s0 + rb) * E + hh * 64);
    uint32_t* orow1 = (uint32_t*)(o_out + (size_t)(b * Ss + s0 + rb + 8) * E + hh * 64);
    #pragma unroll
    for (int nt = 0; nt < 8; nt++) {
        orow0[nt * 4 + cc] = f22h2(o[nt][0] * i0, o[nt][1] * i0);
        orow1[nt * 4 + cc] = f22h2(o[nt][2] * i1, o[nt][3] * i1);
    }
}

// ---------------- host launch ----------------
extern "C" void kernel_launch(void* const* d_in, const int* in_sizes, int n_in,
                              void* d_out, int out_size) {
    const float* x     = (const float*)d_in[0];
    const float* Wq    = (const float*)d_in[1];
    const float* bq    = (const float*)d_in[2];
    const float* Wk    = (const float*)d_in[3];
    const float* bk    = (const float*)d_in[4];
    const float* Wv    = (const float*)d_in[5];
    const float* bv    = (const float*)d_in[6];
    const float* Wo    = (const float*)d_in[7];
    const float* bo    = (const float*)d_in[8];
    const float* ln1_g = (const float*)d_in[9];
    const float* ln1_b = (const float*)d_in[10];
    const float* ln2_g = (const float*)d_in[11];
    const float* ln2_b = (const float*)d_in[12];
    const float* W1    = (const float*)d_in[13];
    const float* b1    = (const float*)d_in[14];
    const float* W2    = (const float*)d_in[15];
    const float* b2    = (const float*)d_in[16];
    float* out = (float*)d_out;

    __half *p_h, *p_qhi, *p_qlo, *p_v, *p_Wqkv, *p_WoT, *p_W1T, *p_W2T, *p_o, *p_h2, *p_m1;
    float *p_k, *p_bqkv, *p_x1;
    cudaGetSymbolAddress((void**)&p_h,    g_h);
    cudaGetSymbolAddress((void**)&p_qhi,  g_qhi);
    cudaGetSymbolAddress((void**)&p_qlo,  g_qlo);
    cudaGetSymbolAddress((void**)&p_k,    g_k);
    cudaGetSymbolAddress((void**)&p_v,    g_v);
    cudaGetSymbolAddress((void**)&p_Wqkv, g_Wqkv);
    cudaGetSymbolAddress((void**)&p_bqkv, g_bqkv);
    cudaGetSymbolAddress((void**)&p_WoT,  g_WoT);
    cudaGetSymbolAddress((void**)&p_W1T,  g_W1T);
    cudaGetSymbolAddress((void**)&p_W2T,  g_W2T);
    cudaGetSymbolAddress((void**)&p_o,    g_o);
    cudaGetSymbolAddress((void**)&p_x1,   g_x1);
    cudaGetSymbolAddress((void**)&p_h2,   g_h2);
    cudaGetSymbolAddress((void**)&p_m1,   g_m1);

    cudaFuncSetAttribute(gemm_h<false, false>, cudaFuncAttributeMaxDynamicSharedMemorySize, GEMMH_SMEM);
    cudaFuncSetAttribute(gemm_h<true,  true>,  cudaFuncAttributeMaxDynamicSharedMemorySize, GEMMH_SMEM);
    cudaFuncSetAttribute(gemm_qkv,             cudaFuncAttributeMaxDynamicSharedMemorySize, GEMMH_SMEM);
    cudaFuncSetAttribute(attn_mma_kernel,      cudaFuncAttributeMaxDynamicSharedMemorySize, ATT_SMEM);

    // 1. pack fused QKV weight (coalesced tiled transpose) + bias; transpose Wo, W1, W2
    pack_qkv2_kernel<<<dim3(E / 64, 2, 48), dim3(32, 8)>>>(Wq, Wk, Wv);
    pack_bias_kernel<<<12, 256>>>(bq, bk, bv);
    transpose_kernel<<<dim3(E / 64, E / 32),  dim3(32, 8)>>>(Wo, p_WoT, E, E);
    transpose_kernel<<<dim3(E / 64, Ff / 32), dim3(32, 8)>>>(W1, p_W1T, E, Ff);
    transpose_kernel<<<dim3(Ff / 64, E / 32), dim3(32, 8)>>>(W2, p_W2T, Ff, E);

    // 2. LN1 (fp16 out)
    ln_kernel<<<NT, 256>>>(x, ln1_g, ln1_b, p_h);

    // 3. fused QKV projection: epilogue pre-splits Q (hi/lo fp16), K fp32, V fp16
    gemm_qkv<<<dim3(3 * E / 128, NT / 128), 256, GEMMH_SMEM>>>(p_h, p_Wqkv, p_bqkv, p_qhi, p_qlo, p_k, p_v);

    // 4. attention (2-term split-fp16 S, fp16 PV) -> fp16 o
    attn_mma_kernel<<<dim3(Ss / 128, H * Bb), 256, ATT_SMEM>>>(p_qhi, p_qlo, p_k, p_v, p_o);

    // 5. output projection + residual (fp32 out)
    gemm_h<false, false><<<dim3(E / 128, NT / 128), 256, GEMMH_SMEM>>>(p_o, p_WoT, bo, x, p_x1, NT, E, E);

    // 6. LN2 (fp16 out)
    ln_kernel<<<NT, 256>>>(p_x1, ln2_g, ln2_b, p_h2);

    // 7. MLP up + ReLU (fp16 out -> feeds MLP down as A)
    gemm_h<true, true><<<dim3(Ff / 128, NT / 128), 256, GEMMH_SMEM>>>(p_h2, p_W1T, b1, nullptr, p_m1, NT, Ff, E);

    // 8. MLP down + residual -> fp32 output
    gemm_h<false, false><<<dim3(E / 128, NT / 128), 256, GEMMH_SMEM>>>(p_m1, p_W2T, b2, p_x1, out, NT, E, Ff);
}

// round 17
// speedup vs baseline: 1.2067x; 1.0134x over previous
#include <cuda_runtime.h>
#include <cuda_fp16.h>
#include <cstdint>
#include <math.h>

#define E    1024
#define Dh   64
#define H    16
#define Ff   4096
#define Bb   2
#define Ss   2048
#define NT   (Bb*Ss)     // 4096 tokens
#define EPS  1e-5f

// ---------------- scratch (static device memory; no allocation) ----------------
__device__ __half g_h   [NT * E];        // LN1 output (fp16)
__device__ __half g_qhi [NT * E];        // Q hi fp16
__device__ __half g_qlo [NT * E];        // Q lo fp16 (residual)
__device__ __half g_k   [NT * E];        // K fp16 (only Khi is used downstream)
__device__ __half g_v   [NT * E];        // V fp16
__device__ __half g_Wqkv[3 * E * E];     // packed W_qkv^T : [3072, 1024] (N,K) fp16
__device__ float  g_bqkv[3 * E];
__device__ __half g_WoT [E * E];         // Wo^T  fp16
__device__ __half g_W1T [Ff * E];        // W1^T  fp16
__device__ __half g_W2T [E * Ff];        // W2^T  fp16
__device__ __half g_o   [NT * E];        // attention out (fp16)
__device__ float  g_x1  [NT * E];        // after first residual (fp32)
__device__ __half g_h2  [NT * E];        // LN2 output (fp16)
__device__ __half g_m1  [NT * Ff];       // relu(h2 @ W1 + b1) (fp16)

// ======================= helpers =======================
__device__ __forceinline__ uint32_t smem_u32(const void* p) {
    uint32_t a;
    asm("{ .reg .u64 t; cvta.to.shared.u64 t, %1; cvt.u32.u64 %0, t; }" : "=r"(a) : "l"(p));
    return a;
}
__device__ __forceinline__ uint32_t f22h2(float a, float b) {
    __half2 h = __floats2half2_rn(a, b);
    return *(uint32_t*)&h;
}
#define CP_ASYNC16(dst, src) \
    asm volatile("cp.async.cg.shared.global [%0], [%1], 16;" :: "r"((uint32_t)(dst)), "l"(src))
#define CP_COMMIT() asm volatile("cp.async.commit_group;" ::: "memory")
#define CP_WAIT0()  asm volatile("cp.async.wait_group 0;" ::: "memory")
#define CP_WAIT1()  asm volatile("cp.async.wait_group 1;" ::: "memory")

#define LDMX4(r0, r1, r2, r3, addr) \
    asm volatile("ldmatrix.sync.aligned.m8n8.x4.shared.b16 {%0,%1,%2,%3}, [%4];" \
        : "=r"(r0), "=r"(r1), "=r"(r2), "=r"(r3) : "r"(addr))
#define LDMX4T(r0, r1, r2, r3, addr) \
    asm volatile("ldmatrix.sync.aligned.m8n8.x4.trans.shared.b16 {%0,%1,%2,%3}, [%4];" \
        : "=r"(r0), "=r"(r1), "=r"(r2), "=r"(r3) : "r"(addr))

// m16n8k16 fp16 mma: D(f32) += A(f16) * B(f16)
__device__ __forceinline__ void mma_f16(float* c, const uint32_t* a, uint32_t b0, uint32_t b1) {
    asm volatile(
        "mma.sync.aligned.m16n8k16.row.col.f32.f16.f16.f32 "
        "{%0,%1,%2,%3}, {%4,%5,%6,%7}, {%8,%9}, {%0,%1,%2,%3};"
        : "+f"(c[0]), "+f"(c[1]), "+f"(c[2]), "+f"(c[3])
        : "r"(a[0]), "r"(a[1]), "r"(a[2]), "r"(a[3]), "r"(b0), "r"(b1));
}

// ---------------- prolog: coalesced QKV weight pack ----------------
__global__ void pack_qkv2_kernel(const float* __restrict__ Wq, const float* __restrict__ Wk,
                                 const float* __restrict__ Wv) {
    __shared__ float t[32][67];
    int e0 = blockIdx.x * 64;
    int d0 = blockIdx.y * 32;
    int z  = blockIdx.z;
    int wh = z >> 4, h = z & 15;
    const float* W = (wh == 0) ? Wq : (wh == 1) ? Wk : Wv;
    W += (size_t)h * E * Dh;

    int x = threadIdx.x, y = threadIdx.y;
    #pragma unroll
    for (int half = 0; half < 2; half++) {
        __syncthreads();
        #pragma unroll
        for (int i = 0; i < 4; i++) {
            int ee = y + i * 8;       // 0..31
            t[x][ee] = W[(size_t)(e0 + half * 32 + ee) * Dh + d0 + x];
        }
        __syncthreads();
        int ebase = e0 + half * 32;
        #pragma unroll
        for (int i = 0; i < 4; i++) {
            int dd = y + i * 8;           // 0..31
            if ((x & 1) == 0) {
                __half2 hv = __floats2half2_rn(t[dd][x], t[dd][x + 1]);
                *(__half2*)&g_Wqkv[(size_t)(wh * 1024 + h * 64 + d0 + dd) * 1024 + ebase + x] = hv;
            }
        }
    }
}

__global__ void pack_bias_kernel(const float* __restrict__ bq, const float* __restrict__ bk,
                                 const float* __restrict__ bv) {
    int i = blockIdx.x * blockDim.x + threadIdx.x;
    if (i < 3 * E) {
        const float* bs = (i < E) ? bq : (i < 2 * E) ? bk : bv;
        g_bqkv[i] = bs[i % E];
    }
}

// out[n*K + k] = fp16(in[k*N + n]) ; vectorized: 64-wide k tiles, half2 writes
__global__ void transpose_kernel(const float* __restrict__ in, __half* __restrict__ out,
                                 int K, int N) {
    __shared__ float t[32][67];
    int k0 = blockIdx.x * 64, n0 = blockIdx.y * 32;
    int x = threadIdx.x, y = threadIdx.y;     // 32 x 8
    #pragma unroll
    for (int half = 0; half < 2; half++) {
        __syncthreads();
        #pragma unroll
        for (int i = 0; i < 4; i++) {
            int kk = y + i * 8;               // 0..31
            t[x][kk] = in[(size_t)(k0 + half * 32 + kk) * N + n0 + x];
        }
        __syncthreads();
        #pragma unroll
        for (int i = 0; i < 4; i++) {
            int nn = y + i * 8;               // 0..31
            if ((x & 1) == 0) {
                __half2 hv = __floats2half2_rn(t[nn][x], t[nn][x + 1]);
                *(__half2*)&out[(size_t)(n0 + nn) * K + k0 + half * 32 + x] = hv;
            }
        }
    }
}

// ---------------- layernorm (fp16 output) ----------------
__global__ void ln_kernel(const float* __restrict__ x, const float* __restrict__ g,
                          const float* __restrict__ b, __half* __restrict__ out) {
    int row = blockIdx.x;
    int tid = threadIdx.x;
    const float4 v = ((const float4*)(x + (size_t)row * E))[tid];
    float s  = v.x + v.y + v.z + v.w;
    float ss = v.x * v.x + v.y * v.y + v.z * v.z + v.w * v.w;
    #pragma unroll
    for (int o = 16; o; o >>= 1) {
        s  += __shfl_xor_sync(0xffffffffu, s,  o);
        ss += __shfl_xor_sync(0xffffffffu, ss, o);
    }
    __shared__ float sm[8], sm2[8];
    if ((tid & 31) == 0) { sm[tid >> 5] = s; sm2[tid >> 5] = ss; }
    __syncthreads();
    float tot = 0.f, tot2 = 0.f;
    #pragma unroll
    for (int i = 0; i < 8; i++) { tot += sm[i]; tot2 += sm2[i]; }
    float mean = tot * (1.0f / E);
    float var  = tot2 * (1.0f / E) - mean * mean;
    float inv  = rsqrtf(var + EPS);
    const float4 gg = ((const float4*)g)[tid];
    const float4 bb = ((const float4*)b)[tid];
    __half2* orow = (__half2*)(out + (size_t)row * E);
    orow[2 * tid]     = __floats2half2_rn((v.x - mean) * inv * gg.x + bb.x,
                                          (v.y - mean) * inv * gg.y + bb.y);
    orow[2 * tid + 1] = __floats2half2_rn((v.z - mean) * inv * gg.z + bb.z,
                                          (v.w - mean) * inv * gg.w + bb.w);
}

// ---------------- fp16 warp-MMA GEMM core macros ----------------
#define LDH 72
#define TILE_H (128 * LDH * 2)          // 18432 bytes per tile
#define STAGE_H (2 * TILE_H)            // 36864
#define GEMMH_SMEM (3 * STAGE_H)        // 110592 -> 2 CTAs/SM

// generic GEMM: C = A[M,K] @ Bt[N,K]^T (+bias)(+relu)(+res)
template<bool RELU, bool OUT_HALF>
__global__ __launch_bounds__(256, 2)
void gemm_h(const __half* __restrict__ A, const __half* __restrict__ Bt,
            const float* __restrict__ bias, const float* __restrict__ res,
            void* __restrict__ Cv, int M, int N, int K) {
    extern __shared__ char smem[];
    uint32_t sb = smem_u32(smem);
    int tid = threadIdx.x;
    int lane = tid & 31, wid = tid >> 5;
    int warp_m = wid & 3, warp_n = wid >> 2;
    int n0 = blockIdx.x * 128, m0 = blockIdx.y * 128;

    const __half* Abase = A  + (size_t)m0 * K;
    const __half* Bbase = Bt + (size_t)n0 * K;
    int NC = K >> 6;

    int lt = lane >> 3, lr = lane & 7;
    uint32_t aoff[2], boff[4];
    #pragma unroll
    for (int mt = 0; mt < 2; mt++)
        aoff[mt] = ((warp_m * 32 + mt * 16 + (lt & 1) * 8 + lr) * 36 + (lt >> 1) * 4) * 4;
    #pragma unroll
    for (int nt2 = 0; nt2 < 4; nt2++)
        boff[nt2] = TILE_H + ((warp_n * 64 + nt2 * 16 + (lt & 1) * 8 + lr) * 36 + (lt >> 1) * 4) * 4;

    #pragma unroll
    for (int st = 0; st < 2; st++) {
        uint32_t bufo = st * STAGE_H;
        int koff = st * 64;
        #pragma unroll
        for (int i = 0; i < 4; i++) {
            int idx = tid + i * 256;
            int row = idx >> 3, seg = idx & 7;
            CP_ASYNC16(sb + bufo + row * 144 + seg * 16,
                       Abase + (size_t)row * K + koff + seg * 8);
        }
        #pragma unroll
        for (int i = 0; i < 4; i++) {
            int idx = tid + i * 256;
            int row = idx >> 3, seg = idx & 7;
            CP_ASYNC16(sb + bufo + TILE_H + row * 144 + seg * 16,
                       Bbase + (size_t)row * K + koff + seg * 8);
        }
        CP_COMMIT();
    }
    CP_WAIT1();
    __syncthreads();

    float acc[2][8][4] = {};
    int cb = 0, pb = 2;
    int r = lane >> 2, cc = lane & 3;

    for (int c = 0; c < NC; c++) {
        if (c + 2 < NC) {
            uint32_t bufo = pb * STAGE_H;
            const __half* as = Abase + (c + 2) * 64;
            const __half* bs = Bbase + (c + 2) * 64;
            #pragma unroll
            for (int i = 0; i < 4; i++) {
                int idx = tid + i * 256;
                int row = idx >> 3, seg = idx & 7;
                CP_ASYNC16(sb + bufo + row * 144 + seg * 16,
                           as + (size_t)row * K + seg * 8);
            }
            #pragma unroll
            for (int i = 0; i < 4; i++) {
                int idx = tid + i * 256;
                int row = idx >> 3, seg = idx & 7;
                CP_ASYNC16(sb + bufo + TILE_H + row * 144 + seg * 16,
                           bs + (size_t)row * K + seg * 8);
            }
        }
        CP_COMMIT();

        uint32_t stage = sb + cb * STAGE_H;
        #pragma unroll
        for (int kk = 0; kk < 4; kk++) {
            uint32_t koff = kk * 32;
            uint32_t afr[2][4];
            LDMX4(afr[0][0], afr[0][1], afr[0][2], afr[0][3], stage + aoff[0] + koff);
            LDMX4(afr[1][0], afr[1][1], afr[1][2], afr[1][3], stage + aoff[1] + koff);
            #pragma unroll
            for (int nt2 = 0; nt2 < 4; nt2++) {
                uint32_t bfr[4];
                LDMX4(bfr[0], bfr[1], bfr[2], bfr[3], stage + boff[nt2] + koff);
                mma_f16(acc[0][2 * nt2    ], afr[0], bfr[0], bfr[2]);
                mma_f16(acc[1][2 * nt2    ], afr[1], bfr[0], bfr[2]);
                mma_f16(acc[0][2 * nt2 + 1], afr[0], bfr[1], bfr[3]);
                mma_f16(acc[1][2 * nt2 + 1], afr[1], bfr[1], bfr[3]);
            }
        }
        CP_WAIT1();
        __syncthreads();
        cb = (cb + 1 == 3) ? 0 : cb + 1;
        pb = (pb + 1 == 3) ? 0 : pb + 1;
    }

    #pragma unroll
    for (int mt = 0; mt < 2; mt++) {
        #pragma unroll
        for (int nt = 0; nt < 8; nt++) {
            int col = n0 + warp_n * 64 + nt * 8 + cc * 2;
            float2 bv = *(const float2*)&bias[col];
            #pragma unroll
            for (int rr = 0; rr < 2; rr++) {
                int row = m0 + warp_m * 32 + mt * 16 + r + rr * 8;
                float vx = acc[mt][nt][rr * 2 + 0] + bv.x;
                float vy = acc[mt][nt][rr * 2 + 1] + bv.y;
                if (RELU) { vx = fmaxf(vx, 0.f); vy = fmaxf(vy, 0.f); }
                if (res) {
                    float2 rv = *(const float2*)&res[(size_t)row * N + col];
                    vx += rv.x; vy += rv.y;
                }
                if (OUT_HALF) {
                    *(uint32_t*)&((__half*)Cv)[(size_t)row * N + col] = f22h2(vx, vy);
                } else {
                    float2 v = { vx, vy };
                    *(float2*)&((float*)Cv)[(size_t)row * N + col] = v;
                }
            }
        }
    }
}

// QKV GEMM: epilogue splits by region: Q -> qhi/qlo fp16, K -> fp16, V -> fp16
__global__ __launch_bounds__(256, 2)
void gemm_qkv(const __half* __restrict__ A, const __half* __restrict__ Bt,
              const float* __restrict__ bias,
              __half* __restrict__ qhi, __half* __restrict__ qlo,
              __half* __restrict__ kh, __half* __restrict__ vf) {
    const int K = E;
    extern __shared__ char smem[];
    uint32_t sb = smem_u32(smem);
    int tid = threadIdx.x;
    int lane = tid & 31, wid = tid >> 5;
    int warp_m = wid & 3, warp_n = wid >> 2;
    int n0 = blockIdx.x * 128, m0 = blockIdx.y * 128;

    const __half* Abase = A  + (size_t)m0 * K;
    const __half* Bbase = Bt + (size_t)n0 * K;
    int NC = K >> 6;

    int lt = lane >> 3, lr = lane & 7;
    uint32_t aoff[2], boff[4];
    #pragma unroll
    for (int mt = 0; mt < 2; mt++)
        aoff[mt] = ((warp_m * 32 + mt * 16 + (lt & 1) * 8 + lr) * 36 + (lt >> 1) * 4) * 4;
    #pragma unroll
    for (int nt2 = 0; nt2 < 4; nt2++)
        boff[nt2] = TILE_H + ((warp_n * 64 + nt2 * 16 + (lt & 1) * 8 + lr) * 36 + (lt >> 1) * 4) * 4;

    #pragma unroll
    for (int st = 0; st < 2; st++) {
        uint32_t bufo = st * STAGE_H;
        int koff = st * 64;
        #pragma unroll
        for (int i = 0; i < 4; i++) {
            int idx = tid + i * 256;
            int row = idx >> 3, seg = idx & 7;
            CP_ASYNC16(sb + bufo + row * 144 + seg * 16,
                       Abase + (size_t)row * K + koff + seg * 8);
        }
        #pragma unroll
        for (int i = 0; i < 4; i++) {
            int idx = tid + i * 256;
            int row = idx >> 3, seg = idx & 7;
            CP_ASYNC16(sb + bufo + TILE_H + row * 144 + seg * 16,
                       Bbase + (size_t)row * K + koff + seg * 8);
        }
        CP_COMMIT();
    }
    CP_WAIT1();
    __syncthreads();

    float acc[2][8][4] = {};
    int cb = 0, pb = 2;
    int r = lane >> 2, cc = lane & 3;

    for (int c = 0; c < NC; c++) {
        if (c + 2 < NC) {
            uint32_t bufo = pb * STAGE_H;
            const __half* as = Abase + (c + 2) * 64;
            const __half* bs = Bbase + (c + 2) * 64;
            #pragma unroll
            for (int i = 0; i < 4; i++) {
                int idx = tid + i * 256;
                int row = idx >> 3, seg = idx & 7;
                CP_ASYNC16(sb + bufo + row * 144 + seg * 16,
                           as + (size_t)row * K + seg * 8);
            }
            #pragma unroll
            for (int i = 0; i < 4; i++) {
                int idx = tid + i * 256;
                int row = idx >> 3, seg = idx & 7;
                CP_ASYNC16(sb + bufo + TILE_H + row * 144 + seg * 16,
                           bs + (size_t)row * K + seg * 8);
            }
        }
        CP_COMMIT();

        uint32_t stage = sb + cb * STAGE_H;
        #pragma unroll
        for (int kk = 0; kk < 4; kk++) {
            uint32_t koff = kk * 32;
            uint32_t afr[2][4];
            LDMX4(afr[0][0], afr[0][1], afr[0][2], afr[0][3], stage + aoff[0] + koff);
            LDMX4(afr[1][0], afr[1][1], afr[1][2], afr[1][3], stage + aoff[1] + koff);
            #pragma unroll
            for (int nt2 = 0; nt2 < 4; nt2++) {
                uint32_t bfr[4];
                LDMX4(bfr[0], bfr[1], bfr[2], bfr[3], stage + boff[nt2] + koff);
                mma_f16(acc[0][2 * nt2    ], afr[0], bfr[0], bfr[2]);
                mma_f16(acc[1][2 * nt2    ], afr[1], bfr[0], bfr[2]);
                mma_f16(acc[0][2 * nt2 + 1], afr[0], bfr[1], bfr[3]);
                mma_f16(acc[1][2 * nt2 + 1], afr[1], bfr[1], bfr[3]);
            }
        }
        CP_WAIT1();
        __syncthreads();
        cb = (cb + 1 == 3) ? 0 : cb + 1;
        pb = (pb + 1 == 3) ? 0 : pb + 1;
    }

    // epilogue: region 0 = Q (hi/lo fp16), 1 = K (fp16), 2 = V (fp16)
    int region = n0 >> 10;
    #pragma unroll
    for (int mt = 0; mt < 2; mt++) {
        #pragma unroll
        for (int nt = 0; nt < 8; nt++) {
            int col = n0 + warp_n * 64 + nt * 8 + cc * 2;
            float2 bv = *(const float2*)&bias[col];
            int cr = col - region * E;
            #pragma unroll
            for (int rr = 0; rr < 2; rr++) {
                int row = m0 + warp_m * 32 + mt * 16 + r + rr * 8;
                float vx = acc[mt][nt][rr * 2 + 0] + bv.x;
                float vy = acc[mt][nt][rr * 2 + 1] + bv.y;
                size_t off = (size_t)row * E + cr;
                if (region == 1) {
                    *(uint32_t*)&kh[off] = f22h2(vx, vy);
                } else if (region == 2) {
                    *(uint32_t*)&vf[off] = f22h2(vx, vy);
                } else {
                    __half hx = __float2half_rn(vx), hy = __float2half_rn(vy);
                    __half2 hh2; hh2.x = hx; hh2.y = hy;
                    *(__half2*)&qhi[off] = hh2;
                    *(uint32_t*)&qlo[off] = f22h2(vx - __half2float(hx),
                                                  vy - __half2float(hy));
                }
            }
        }
    }
}

// ---------------- fp16 MMA flash attention (rows = keys, softmax over queries) --
// CTA: 128 key rows, 8 warps. All operands arrive fp16; K frags via ldmatrix.
// smem: QHI 2x9216 | QLO 2x9216 | VH 2x9216 | K 128x72h (18432, reused as P)
#define AQHI_B 0
#define AQLO_B 18432
#define AVH_B  36864
#define AKP_B  55296
#define ATT_SMEM (AKP_B + 18432)   // 73728 bytes

__global__ __launch_bounds__(256)
void attn_mma_kernel(const __half* __restrict__ qhi_g, const __half* __restrict__ qlo_g,
                     const __half* __restrict__ k_g, const __half* __restrict__ v_g,
                     __half* __restrict__ o_out) {
    extern __shared__ float smf[];
    uint32_t sb = smem_u32(smf);
    uint32_t* smu = (uint32_t*)smf;

    int hb = blockIdx.y;
    int hh = hb >> 1, b = hb & 1;
    int s0 = blockIdx.x * 128;
    int tid = threadIdx.x, lane = tid & 31, wid = tid >> 5;
    int r = lane >> 2, cc = lane & 3;
    int rb = wid * 16 + r;

    // ldmatrix per-thread byte offsets
    int lt = lane >> 3, lr = lane & 7;
    uint32_t qhio[4], qloo[4], vofft[4], poff;
    {
        uint32_t rowsel = (lt & 1) * 8 + lr;
        uint32_t wordsel = (lt >> 1) * 4;
        #pragma unroll
        for (int nt2 = 0; nt2 < 4; nt2++) {
            uint32_t ro = ((nt2 * 16 + rowsel) * 36 + wordsel) * 4;   // B frags (n-rows)
            qhio[nt2] = AQHI_B + ro;
            qloo[nt2] = AQLO_B + ro;
            // V trans: rows = t (k dim), col bytes = d offset
            vofft[nt2] = AVH_B + rowsel * 144 + nt2 * 32 + (lt >> 1) * 16;
        }
        // A-frag offset within K/P region (identical formula for K frags and P frags)
        poff = AKP_B + ((wid * 16 + rowsel) * 36 + wordsel) * 4;
    }

    size_t tok0 = (size_t)(b * Ss);
    const __half* kbase = k_g   + (tok0 + s0) * E + hh * 64;
    const __half* qh_b  = qhi_g + tok0 * E + hh * 64;
    const __half* ql_b  = qlo_g + tok0 * E + hh * 64;
    const __half* v_b   = v_g   + tok0 * E + hh * 64;

    // K tile [128 x 64] fp16 (1024 16B slots)
    #pragma unroll
    for (int i = 0; i < 4; i++) {
        int idx = tid + i * 256;
        int row = idx >> 3, seg = idx & 7;
        CP_ASYNC16(sb + AKP_B + row * 144 + seg * 16,
                   kbase + (size_t)row * E + seg * 8);
    }
    // Qhi/Qlo/V tile 0 -> buffer 0 (512 slots each)
    #pragma unroll
    for (int i = 0; i < 2; i++) {
        int idx = tid + i * 256;
        int row = idx >> 3, seg = idx & 7;
        uint32_t doff = row * 144 + seg * 16;
        const size_t goff = (size_t)row * E + seg * 8;
        CP_ASYNC16(sb + AQHI_B + doff, qh_b + goff);
        CP_ASYNC16(sb + AQLO_B + doff, ql_b + goff);
        CP_ASYNC16(sb + AVH_B  + doff, v_b  + goff);
    }
    CP_COMMIT();
    CP_WAIT0();              // K and tile-0 operands all resident
    __syncthreads();

    // Khi fragments via ldmatrix (A-operand layout): m16 x k64 (4 k16-steps)
    uint32_t kfh[4][4];
    #pragma unroll
    for (int kk = 0; kk < 4; kk++)
        LDMX4(kfh[kk][0], kfh[kk][1], kfh[kk][2], kfh[kk][3], sb + poff + kk * 32);
    __syncthreads();          // K region now reusable as P

    float mrow0 = -1e30f, mrow1 = -1e30f, lrow0 = 0.f, lrow1 = 0.f;
    float o[8][4] = {};

    for (int t0 = 0; t0 < Ss; t0 += 64) {
        int buf = (t0 >> 6) & 1;
        uint32_t bufo = buf * 9216;
        if (t0 + 64 < Ss) {
            uint32_t nbo = (buf ^ 1) * 9216;
            size_t src0 = (size_t)(t0 + 64) * E;
            #pragma unroll
            for (int i = 0; i < 2; i++) {
                int idx = tid + i * 256;
                int row = idx >> 3, seg = idx & 7;
                uint32_t doff = nbo + row * 144 + seg * 16;
                const size_t goff = src0 + (size_t)row * E + seg * 8;
                CP_ASYNC16(sb + AQHI_B + doff, qh_b + goff);
                CP_ASYNC16(sb + AQLO_B + doff, ql_b + goff);
                CP_ASYNC16(sb + AVH_B  + doff, v_b  + goff);
            }
            CP_COMMIT();
        }

        // S = Khi x (Qhi + Qlo)^T : 2 MMAs per k16-step
        float s[8][4] = {};
        #pragma unroll
        for (int kk = 0; kk < 4; kk++) {
            uint32_t koff = bufo + kk * 32;
            #pragma unroll
            for (int nt2 = 0; nt2 < 4; nt2++) {
                uint32_t qh[4], ql[4];
                LDMX4(qh[0], qh[1], qh[2], qh[3], sb + qhio[nt2] + koff);
                LDMX4(ql[0], ql[1], ql[2], ql[3], sb + qloo[nt2] + koff);
                mma_f16(s[2 * nt2    ], kfh[kk], qh[0], qh[2]);
                mma_f16(s[2 * nt2    ], kfh[kk], ql[0], ql[2]);
                mma_f16(s[2 * nt2 + 1], kfh[kk], qh[1], qh[3]);
                mma_f16(s[2 * nt2 + 1], kfh[kk], ql[1], ql[3]);
            }
        }

        // online softmax over t (rows in-warp: quad shfl reduce)
        float mx0 = -1e30f, mx1 = -1e30f;
        #pragma unroll
        for (int nt = 0; nt < 8; nt++) {
            mx0 = fmaxf(mx0, fmaxf(s[nt][0], s[nt][1]));
            mx1 = fmaxf(mx1, fmaxf(s[nt][2], s[nt][3]));
        }
        mx0 = fmaxf(mx0, __shfl_xor_sync(0xffffffffu, mx0, 1));
        mx0 = fmaxf(mx0, __shfl_xor_sync(0xffffffffu, mx0, 2));
        mx1 = fmaxf(mx1, __shfl_xor_sync(0xffffffffu, mx1, 1));
        mx1 = fmaxf(mx1, __shfl_xor_sync(0xffffffffu, mx1, 2));
        float mn0 = fmaxf(mrow0, mx0), mn1 = fmaxf(mrow1, mx1);
        float a0 = __expf(mrow0 - mn0), a1 = __expf(mrow1 - mn1);
        mrow0 = mn0; mrow1 = mn1;

        float ps0 = 0.f, ps1 = 0.f;
        #pragma unroll
        for (int nt = 0; nt < 8; nt++) {
            float p0 = __expf(s[nt][0] - mn0);
            float p1 = __expf(s[nt][1] - mn0);
            float p2 = __expf(s[nt][2] - mn1);
            float p3 = __expf(s[nt][3] - mn1);
            ps0 += p0 + p1;
            ps1 += p2 + p3;
            smu[AKP_B / 4 + (rb    ) * 36 + nt * 4 + cc] = f22h2(p0, p1);
            smu[AKP_B / 4 + (rb + 8) * 36 + nt * 4 + cc] = f22h2(p2, p3);
        }
        ps0 += __shfl_xor_sync(0xffffffffu, ps0, 1);
        ps0 += __shfl_xor_sync(0xffffffffu, ps0, 2);
        ps1 += __shfl_xor_sync(0xffffffffu, ps1, 1);
        ps1 += __shfl_xor_sync(0xffffffffu, ps1, 2);
        lrow0 = lrow0 * a0 + ps0;
        lrow1 = lrow1 * a1 + ps1;
        #pragma unroll
        for (int nt = 0; nt < 8; nt++) {
            o[nt][0] *= a0; o[nt][1] *= a0;
            o[nt][2] *= a1; o[nt][3] *= a1;
        }
        __syncwarp();   // this warp's P rows visible (warp-private rows)

        // O += P x V : P A-frags via ldmatrix, V B-frags via ldmatrix.trans
        #pragma unroll
        for (int kk = 0; kk < 4; kk++) {
            uint32_t pa[4];
            LDMX4(pa[0], pa[1], pa[2], pa[3], sb + poff + kk * 32);
            uint32_t vko = bufo + kk * 2304;       // 16 t-rows * 144B
            #pragma unroll
            for (int nt2 = 0; nt2 < 4; nt2++) {
                uint32_t vf[4];
                LDMX4T(vf[0], vf[1], vf[2], vf[3], sb + vofft[nt2] + vko);
                mma_f16(o[2 * nt2    ], pa, vf[0], vf[1]);
                mma_f16(o[2 * nt2 + 1], pa, vf[2], vf[3]);
            }
        }
        CP_WAIT0();
        __syncthreads();    // next tiles resident; all warps done with buf
    }

    float i0 = 1.f / lrow0, i1 = 1.f / lrow1;
    uint32_t* orow0 = (uint32_t*)(o_out + (size_t)(b * Ss + s0 + rb) * E + hh * 64);
    uint32_t* orow1 = (uint32_t*)(o_out + (size_t)(b * Ss + s0 + rb + 8) * E + hh * 64);
    #pragma unroll
    for (int nt = 0; nt < 8; nt++) {
        orow0[nt * 4 + cc] = f22h2(o[nt][0] * i0, o[nt][1] * i0);
        orow1[nt * 4 + cc] = f22h2(o[nt][2] * i1, o[nt][3] * i1);
    }
}

// ---------------- host launch ----------------
extern "C" void kernel_launch(void* const* d_in, const int* in_sizes, int n_in,
                              void* d_out, int out_size) {
    const float* x     = (const float*)d_in[0];
    const float* Wq    = (const float*)d_in[1];
    const float* bq    = (const float*)d_in[2];
    const float* Wk    = (const float*)d_in[3];
    const float* bk    = (const float*)d_in[4];
    const float* Wv    = (const float*)d_in[5];
    const float* bv    = (const float*)d_in[6];
    const float* Wo    = (const float*)d_in[7];
    const float* bo    = (const float*)d_in[8];
    const float* ln1_g = (const float*)d_in[9];
    const float* ln1_b = (const float*)d_in[10];
    const float* ln2_g = (const float*)d_in[11];
    const float* ln2_b = (const float*)d_in[12];
    const float* W1    = (const float*)d_in[13];
    const float* b1    = (const float*)d_in[14];
    const float* W2    = (const float*)d_in[15];
    const float* b2    = (const float*)d_in[16];
    float* out = (float*)d_out;

    __half *p_h, *p_qhi, *p_qlo, *p_k, *p_v, *p_Wqkv, *p_WoT, *p_W1T, *p_W2T, *p_o, *p_h2, *p_m1;
    float *p_bqkv, *p_x1;
    cudaGetSymbolAddress((void**)&p_h,    g_h);
    cudaGetSymbolAddress((void**)&p_qhi,  g_qhi);
    cudaGetSymbolAddress((void**)&p_qlo,  g_qlo);
    cudaGetSymbolAddress((void**)&p_k,    g_k);
    cudaGetSymbolAddress((void**)&p_v,    g_v);
    cudaGetSymbolAddress((void**)&p_Wqkv, g_Wqkv);
    cudaGetSymbolAddress((void**)&p_bqkv, g_bqkv);
    cudaGetSymbolAddress((void**)&p_WoT,  g_WoT);
    cudaGetSymbolAddress((void**)&p_W1T,  g_W1T);
    cudaGetSymbolAddress((void**)&p_W2T,  g_W2T);
    cudaGetSymbolAddress((void**)&p_o,    g_o);
    cudaGetSymbolAddress((void**)&p_x1,   g_x1);
    cudaGetSymbolAddress((void**)&p_h2,   g_h2);
    cudaGetSymbolAddress((void**)&p_m1,   g_m1);

    cudaFuncSetAttribute(gemm_h<false, false>, cudaFuncAttributeMaxDynamicSharedMemorySize, GEMMH_SMEM);
    cudaFuncSetAttribute(gemm_h<true,  true>,  cudaFuncAttributeMaxDynamicSharedMemorySize, GEMMH_SMEM);
    cudaFuncSetAttribute(gemm_qkv,             cudaFuncAttributeMaxDynamicSharedMemorySize, GEMMH_SMEM);
    cudaFuncSetAttribute(attn_mma_kernel,      cudaFuncAttributeMaxDynamicSharedMemorySize, ATT_SMEM);

    // 1. pack fused QKV weight (coalesced tiled transpose) + bias; transpose Wo, W1, W2
    pack_qkv2_kernel<<<dim3(E / 64, 2, 48), dim3(32, 8)>>>(Wq, Wk, Wv);
    pack_bias_kernel<<<12, 256>>>(bq, bk, bv);
    transpose_kernel<<<dim3(E / 64, E / 32),  dim3(32, 8)>>>(Wo, p_WoT, E, E);
    transpose_kernel<<<dim3(E / 64, Ff / 32), dim3(32, 8)>>>(W1, p_W1T, E, Ff);
    transpose_kernel<<<dim3(Ff / 64, E / 32), dim3(32, 8)>>>(W2, p_W2T, Ff, E);

    // 2. LN1 (fp16 out)
    ln_kernel<<<NT, 256>>>(x, ln1_g, ln1_b, p_h);

    // 3. fused QKV projection: epilogue pre-splits Q (hi/lo fp16), K fp16, V fp16
    gemm_qkv<<<dim3(3 * E / 128, NT / 128), 256, GEMMH_SMEM>>>(p_h, p_Wqkv, p_bqkv, p_qhi, p_qlo, p_k, p_v);

    // 4. attention (2-term split-fp16 S, fp16 PV) -> fp16 o
    attn_mma_kernel<<<dim3(Ss / 128, H * Bb), 256, ATT_SMEM>>>(p_qhi, p_qlo, p_k, p_v, p_o);

    // 5. output projection + residual (fp32 out)
    gemm_h<false, false><<<dim3(E / 128, NT / 128), 256, GEMMH_SMEM>>>(p_o, p_WoT, bo, x, p_x1, NT, E, E);

    // 6. LN2 (fp16 out)
    ln_kernel<<<NT, 256>>>(p_x1, ln2_g, ln2_b, p_h2);

    // 7. MLP up + ReLU (fp16 out -> feeds MLP down as A)
    gemm_h<true, true><<<dim3(Ff / 128, NT / 128), 256, GEMMH_SMEM>>>(p_h2, p_W1T, b1, nullptr, p_m1, NT, Ff, E);

    // 8. MLP down + residual -> fp32 output
    gemm_h<false, false><<<dim3(E / 128, NT / 128), 256, GEMMH_SMEM>>>(p_m1, p_W2T, b2, p_x1, out, NT, E, Ff);
}